// round 3
// baseline (speedup 1.0000x reference)
#include <cuda_runtime.h>
#include <cstdint>

#define D_ 512
#define P_ 1024
#define E_ 256
#define OUT_ 500

// ---------------- device scratch ----------------
__device__ float g_p[P_ * D_];
__device__ float g_e[E_ * D_];
__device__ float g_pp[P_ * D_];
__device__ float g_ee[E_ * D_];
__device__ float g_wt[512 * 512];   // l2_w transposed [n,k], tf32-rounded, n padded to 512

// ---------------- helpers ----------------
__device__ __forceinline__ uint32_t tf32_bits(float x) {
    uint32_t u;
    asm("cvt.rna.tf32.f32 %0, %1;" : "=r"(u) : "f"(x));
    return u;
}
__device__ __forceinline__ float tf32_val(float x) {
    return __uint_as_float(tf32_bits(x));
}
// D += A*B : m16n8k8 tf32 (sm_80 baseline PTX -> safe for compute_103)
__device__ __forceinline__ void mma8(float* d, const uint32_t* a, const uint32_t* b) {
    asm volatile(
        "mma.sync.aligned.m16n8k8.row.col.f32.tf32.tf32.f32 "
        "{%0,%1,%2,%3}, {%4,%5,%6,%7}, {%8,%9}, {%0,%1,%2,%3};"
        : "+f"(d[0]), "+f"(d[1]), "+f"(d[2]), "+f"(d[3])
        : "r"(a[0]), "r"(a[1]), "r"(a[2]), "r"(a[3]), "r"(b[0]), "r"(b[1]));
}

// ---------------- prep: Wt[n,k] = tf32(l2_w[k,n]), zero-pad n>=500 ----------------
__global__ __launch_bounds__(256) void prep_wt(const float* __restrict__ l2w,
                                               float* __restrict__ wt) {
    int idx = blockIdx.x * 256 + threadIdx.x;  // 512*512, contiguous writes
    int n = idx >> 9, k = idx & 511;
    float v = (n < OUT_) ? l2w[k * OUT_ + n] : 0.0f;
    wt[idx] = tf32_val(v);
}

// ---------------- fp32 SGEMM: C = A[M,K]@B[K,N] (+bias), BM=BN=64 BK=16 ----------------
__global__ __launch_bounds__(256) void sgemm_k(const float* __restrict__ A,
                                               const float* __restrict__ B,
                                               const float* __restrict__ bias,
                                               float* __restrict__ C,
                                               int M, int N, int K) {
    __shared__ float As[16][64];
    __shared__ float Bs[16][64];
    int tid = threadIdx.x;
    int bm = blockIdx.y * 64, bn = blockIdx.x * 64;
    int tx = tid & 15, ty = tid >> 4;
    float acc[4][4];
#pragma unroll
    for (int i = 0; i < 4; i++)
#pragma unroll
        for (int j = 0; j < 4; j++) acc[i][j] = 0.0f;

    int ar = tid >> 2, ak = (tid & 3) * 4;
    int br = tid >> 4, bc = (tid & 15) * 4;
    for (int k0 = 0; k0 < K; k0 += 16) {
        float4 a = *(const float4*)(A + (size_t)(bm + ar) * K + k0 + ak);
        As[ak + 0][ar] = a.x; As[ak + 1][ar] = a.y;
        As[ak + 2][ar] = a.z; As[ak + 3][ar] = a.w;
        *(float4*)&Bs[br][bc] = *(const float4*)(B + (size_t)(k0 + br) * N + bn + bc);
        __syncthreads();
#pragma unroll
        for (int kk = 0; kk < 16; kk++) {
            float4 av = *(const float4*)&As[kk][ty * 4];
            float4 bv = *(const float4*)&Bs[kk][tx * 4];
            acc[0][0] += av.x * bv.x; acc[0][1] += av.x * bv.y;
            acc[0][2] += av.x * bv.z; acc[0][3] += av.x * bv.w;
            acc[1][0] += av.y * bv.x; acc[1][1] += av.y * bv.y;
            acc[1][2] += av.y * bv.z; acc[1][3] += av.y * bv.w;
            acc[2][0] += av.z * bv.x; acc[2][1] += av.z * bv.y;
            acc[2][2] += av.z * bv.z; acc[2][3] += av.z * bv.w;
            acc[3][0] += av.w * bv.x; acc[3][1] += av.w * bv.y;
            acc[3][2] += av.w * bv.z; acc[3][3] += av.w * bv.w;
        }
        __syncthreads();
    }
    int col = bn + tx * 4;
    float4 bb = make_float4(0.f, 0.f, 0.f, 0.f);
    if (bias) bb = *(const float4*)(bias + col);
#pragma unroll
    for (int i = 0; i < 4; i++) {
        float4 v;
        v.x = acc[i][0] + bb.x; v.y = acc[i][1] + bb.y;
        v.z = acc[i][2] + bb.z; v.w = acc[i][3] + bb.w;
        *(float4*)(C + (size_t)(bm + ty * 4 + i) * N + col) = v;
    }
}

// ---------------- main kernel: mma.sync tf32 ----------------
// CTA = (2 p, 128 e, 128 n). 512 threads = 16 warps = (2p x 4e x 2n),
// warp tile 32e x 64n. A = relu(ee+pp) built in registers per k-step.
// grid = 4096: bid = pg*8 + eh*4 + nt
#define SEE 36   // smem row stride (floats): bank = 4g+t -> conflict-free frags

__global__ __launch_bounds__(512, 1) void big_kernel(const float* __restrict__ pp,
                                                     const float* __restrict__ ee,
                                                     const float* __restrict__ wt,
                                                     const float* __restrict__ bias,
                                                     float* __restrict__ out) {
    __shared__ float ee_s[128 * SEE];
    __shared__ float b_s[128 * SEE];
    __shared__ float pp_s[2 * 512];
    __shared__ float bias_s[128];

    const int tid = threadIdx.x;
    const int bid = blockIdx.x;
    const int nt = bid & 3, eh = (bid >> 2) & 1, pg = bid >> 3;
    const int n0 = nt * 128, e0 = eh * 128, p0 = pg * 2;

    const int wid = tid >> 5, lane = tid & 31;
    const int g = lane >> 2, t = lane & 3;
    const int p_i = wid >> 3;              // 0..1
    const int e_w = ((wid >> 1) & 3) * 32; // 0,32,64,96
    const int n_w = (wid & 1) * 64;        // 0,64

    // one-time loads
    for (int i = tid; i < 1024; i += 512)
        pp_s[i] = pp[(size_t)(p0 + (i >> 9)) * 512 + (i & 511)];
    if (tid < 128) bias_s[tid] = (n0 + tid < OUT_) ? bias[n0 + tid] : 0.0f;

    float acc[2][8][4];
#pragma unroll
    for (int mi = 0; mi < 2; mi++)
#pragma unroll
        for (int ni = 0; ni < 8; ni++)
#pragma unroll
            for (int j = 0; j < 4; j++) acc[mi][ni][j] = 0.0f;

    // per-thread staging slots: rows row0 and row0+64, 4-float group c4
    const int row0 = tid >> 3, c4 = (tid & 7) * 4;
    const float* ee_g = ee + (size_t)(e0 + row0) * 512 + c4;
    const float* wt_g = wt + (size_t)(n0 + row0) * 512 + c4;
    const int so0 = row0 * SEE + c4, so1 = (row0 + 64) * SEE + c4;

    float4 re0 = *(const float4*)(ee_g);
    float4 re1 = *(const float4*)(ee_g + 64 * 512);
    float4 rb0 = *(const float4*)(wt_g);
    float4 rb1 = *(const float4*)(wt_g + 64 * 512);

    for (int c = 0; c < 16; ++c) {
        __syncthreads();   // previous chunk fully consumed (and 1st: pp_s/bias ready)
        *(float4*)&ee_s[so0] = re0;
        *(float4*)&ee_s[so1] = re1;
        *(float4*)&b_s[so0]  = rb0;
        *(float4*)&b_s[so1]  = rb1;
        __syncthreads();

        if (c < 15) {   // prefetch next chunk while computing this one
            int k0 = (c + 1) * 32;
            re0 = *(const float4*)(ee_g + k0);
            re1 = *(const float4*)(ee_g + 64 * 512 + k0);
            rb0 = *(const float4*)(wt_g + k0);
            rb1 = *(const float4*)(wt_g + 64 * 512 + k0);
        }

        const float* ppc = &pp_s[p_i * 512 + c * 32];
#pragma unroll
        for (int ks = 0; ks < 4; ++ks) {
            const int kk = ks * 8;
            const float pa = ppc[kk + t];
            const float pb = ppc[kk + t + 4];
            uint32_t a[2][4];
#pragma unroll
            for (int mi = 0; mi < 2; ++mi) {
                const float* er0 = &ee_s[(e_w + mi * 16 + g) * SEE + kk];
                const float* er1 = er0 + 8 * SEE;
                a[mi][0] = tf32_bits(fmaxf(er0[t] + pa, 0.0f));
                a[mi][1] = tf32_bits(fmaxf(er1[t] + pa, 0.0f));
                a[mi][2] = tf32_bits(fmaxf(er0[t + 4] + pb, 0.0f));
                a[mi][3] = tf32_bits(fmaxf(er1[t + 4] + pb, 0.0f));
            }
#pragma unroll
            for (int ni = 0; ni < 8; ++ni) {
                const float* br = &b_s[(n_w + ni * 8 + g) * SEE + kk];
                uint32_t b[2];
                b[0] = __float_as_uint(br[t]);
                b[1] = __float_as_uint(br[t + 4]);
                mma8(acc[0][ni], a[0], b);
                mma8(acc[1][ni], a[1], b);
            }
        }
    }

    // epilogue: bias + relu, float2 stores (rows = 2000B -> 8B aligned)
    const int ebase = e0 + e_w + g;
    const size_t prow = (size_t)(p0 + p_i) * E_;
#pragma unroll
    for (int mi = 0; mi < 2; ++mi) {
        float* r0 = out + (prow + ebase + mi * 16) * OUT_;
#pragma unroll
        for (int ni = 0; ni < 8; ++ni) {
            const int ncl = n_w + ni * 8 + 2 * t;   // even, 0..126
            const int n = n0 + ncl;
            if (n < OUT_) {
                const float bz0 = bias_s[ncl], bz1 = bias_s[ncl + 1];
                float2 v0, v1;
                v0.x = fmaxf(acc[mi][ni][0] + bz0, 0.0f);
                v0.y = fmaxf(acc[mi][ni][1] + bz1, 0.0f);
                v1.x = fmaxf(acc[mi][ni][2] + bz0, 0.0f);
                v1.y = fmaxf(acc[mi][ni][3] + bz1, 0.0f);
                *(float2*)(r0 + n) = v0;
                *(float2*)(r0 + 8 * OUT_ + n) = v1;
            }
        }
    }
}

// ---------------- launch ----------------
extern "C" void kernel_launch(void* const* d_in, const int* in_sizes, int n_in,
                              void* d_out, int out_size) {
    const float* post  = (const float*)d_in[0];
    const float* emoji = (const float*)d_in[1];
    const float* k1_w  = (const float*)d_in[2];
    const float* k1_b  = (const float*)d_in[3];
    const float* k2_w  = (const float*)d_in[4];
    const float* k2_b  = (const float*)d_in[5];
    const float* l1_w  = (const float*)d_in[6];
    const float* l1_b  = (const float*)d_in[7];
    const float* l2_w  = (const float*)d_in[8];
    const float* l2_b  = (const float*)d_in[9];
    float* out = (float*)d_out;

    float *pP, *pE, *pPP, *pEE, *pWT;
    cudaGetSymbolAddress((void**)&pP, g_p);
    cudaGetSymbolAddress((void**)&pE, g_e);
    cudaGetSymbolAddress((void**)&pPP, g_pp);
    cudaGetSymbolAddress((void**)&pEE, g_ee);
    cudaGetSymbolAddress((void**)&pWT, g_wt);

    // p = post@k1_w + k1_b ; e = emoji@k2_w + k2_b
    sgemm_k<<<dim3(8, 16), 256>>>(post, k1_w, k1_b, pP, P_, D_, D_);
    sgemm_k<<<dim3(8, 4), 256>>>(emoji, k2_w, k2_b, pE, E_, D_, D_);
    // pp = p@l1_w[:D] ; ee = e@l1_w[D:] + l1_b
    sgemm_k<<<dim3(8, 16), 256>>>(pP, l1_w, nullptr, pPP, P_, D_, D_);
    sgemm_k<<<dim3(8, 4), 256>>>(pE, l1_w + (size_t)D_ * D_, l1_b, pEE, E_, D_, D_);
    prep_wt<<<1024, 256>>>(l2_w, pWT);
    // main pairwise GEMM
    big_kernel<<<4096, 512>>>(pPP, pEE, pWT, l2_b, out);
}

// round 4
// speedup vs baseline: 2.0207x; 2.0207x over previous
#include <cuda_runtime.h>
#include <cuda_fp16.h>
#include <cstdint>

#define D_ 512
#define P_ 1024
#define E_ 256
#define OUT_ 500

// ---------------- device scratch ----------------
__device__ float g_p[P_ * D_];
__device__ float g_e[E_ * D_];
__device__ float g_pp[P_ * D_];
__device__ float g_ee[E_ * D_];
// l2_w transposed [n][k] as fp16, n padded to 512, k permuted within each
// 16-block so a thread's m16n8k16 B-fragment {2t,2t+1,2t+8,2t+9} is contiguous.
__device__ __half g_wth[512 * 512];

// ---------------- helpers ----------------
// D += A*B : m16n8k16 f16 with f32 accumulate (sm_80 baseline PTX)
__device__ __forceinline__ void mma16(float* d, const uint32_t* a, const uint32_t* b) {
    asm volatile(
        "mma.sync.aligned.m16n8k16.row.col.f32.f16.f16.f32 "
        "{%0,%1,%2,%3}, {%4,%5,%6,%7}, {%8,%9}, {%0,%1,%2,%3};"
        : "+f"(d[0]), "+f"(d[1]), "+f"(d[2]), "+f"(d[3])
        : "r"(a[0]), "r"(a[1]), "r"(a[2]), "r"(a[3]), "r"(b[0]), "r"(b[1]));
}
__device__ __forceinline__ uint32_t pack_relu_h2(float lo, float hi) {
    __half2 h = __floats2half2_rn(fmaxf(lo, 0.0f), fmaxf(hi, 0.0f));
    return *(uint32_t*)&h;
}

// ---------------- shared fp32 SGEMM body: C = A[M,K]@B[K,N] (+bias) ----------------
// BM=BN=64, BK=16, 256 threads. Caller guarantees uniform block-level guards.
__device__ __forceinline__ void sgemm_body(const float* __restrict__ A,
                                           const float* __restrict__ B,
                                           const float* __restrict__ bias,
                                           float* __restrict__ C,
                                           int M, int N, int K) {
    __shared__ float As[16][64];
    __shared__ float Bs[16][64];
    int tid = threadIdx.x;
    int bm = blockIdx.y * 64, bn = blockIdx.x * 64;
    int tx = tid & 15, ty = tid >> 4;
    float acc[4][4];
#pragma unroll
    for (int i = 0; i < 4; i++)
#pragma unroll
        for (int j = 0; j < 4; j++) acc[i][j] = 0.0f;

    int ar = tid >> 2, ak = (tid & 3) * 4;
    int br = tid >> 4, bc = (tid & 15) * 4;
    for (int k0 = 0; k0 < K; k0 += 16) {
        float4 a = *(const float4*)(A + (size_t)(bm + ar) * K + k0 + ak);
        As[ak + 0][ar] = a.x; As[ak + 1][ar] = a.y;
        As[ak + 2][ar] = a.z; As[ak + 3][ar] = a.w;
        *(float4*)&Bs[br][bc] = *(const float4*)(B + (size_t)(k0 + br) * N + bn + bc);
        __syncthreads();
#pragma unroll
        for (int kk = 0; kk < 16; kk++) {
            float4 av = *(const float4*)&As[kk][ty * 4];
            float4 bv = *(const float4*)&Bs[kk][tx * 4];
            acc[0][0] += av.x * bv.x; acc[0][1] += av.x * bv.y;
            acc[0][2] += av.x * bv.z; acc[0][3] += av.x * bv.w;
            acc[1][0] += av.y * bv.x; acc[1][1] += av.y * bv.y;
            acc[1][2] += av.y * bv.z; acc[1][3] += av.y * bv.w;
            acc[2][0] += av.z * bv.x; acc[2][1] += av.z * bv.y;
            acc[2][2] += av.z * bv.z; acc[2][3] += av.z * bv.w;
            acc[3][0] += av.w * bv.x; acc[3][1] += av.w * bv.y;
            acc[3][2] += av.w * bv.z; acc[3][3] += av.w * bv.w;
        }
        __syncthreads();
    }
    int col = bn + tx * 4;
    float4 bb = make_float4(0.f, 0.f, 0.f, 0.f);
    if (bias) bb = *(const float4*)(bias + col);
#pragma unroll
    for (int i = 0; i < 4; i++) {
        float4 v;
        v.x = acc[i][0] + bb.x; v.y = acc[i][1] + bb.y;
        v.z = acc[i][2] + bb.z; v.w = acc[i][3] + bb.w;
        *(float4*)(C + (size_t)(bm + ty * 4 + i) * N + col) = v;
    }
}

// ---------------- fused launch 1: p-gemm, e-gemm, Wt prep ----------------
__global__ __launch_bounds__(256) void fused1(const float* __restrict__ post,
                                              const float* __restrict__ k1w,
                                              const float* __restrict__ k1b,
                                              const float* __restrict__ emoji,
                                              const float* __restrict__ k2w,
                                              const float* __restrict__ k2b,
                                              const float* __restrict__ l2w,
                                              float* __restrict__ pP,
                                              float* __restrict__ pE,
                                              __half* __restrict__ wth) {
    int z = blockIdx.z;
    if (z == 2) {
        // build g_wth[n][perm(k)] = fp16(l2w[k][n]); 512x512 over 128 blocks
        int b = blockIdx.y * gridDim.x + blockIdx.x;  // 0..127
        int base = b * 2048;
#pragma unroll
        for (int it = 0; it < 8; it++) {
            int idx = base + it * 256 + threadIdx.x;
            int n = idx >> 9, j = idx & 511;
            int k16 = j >> 4, jj = j & 15;
            int t = jj >> 2, r = jj & 3;
            int ks = k16 * 16 + 2 * t + ((r >> 1) << 3) + (r & 1);
            float v = (n < OUT_) ? l2w[ks * OUT_ + n] : 0.0f;
            wth[idx] = __float2half_rn(v);
        }
        return;
    }
    if (z == 0) {
        sgemm_body(post, k1w, k1b, pP, P_, D_, D_);
    } else {
        if (blockIdx.y >= 4) return;  // M=256 -> 4 y-blocks
        sgemm_body(emoji, k2w, k2b, pE, E_, D_, D_);
    }
}

// ---------------- fused launch 2: pp-gemm, ee-gemm ----------------
__global__ __launch_bounds__(256) void fused2(const float* __restrict__ pP,
                                              const float* __restrict__ pE,
                                              const float* __restrict__ l1w,
                                              const float* __restrict__ l1b,
                                              float* __restrict__ pPP,
                                              float* __restrict__ pEE) {
    if (blockIdx.z == 0) {
        sgemm_body(pP, l1w, nullptr, pPP, P_, D_, D_);
    } else {
        if (blockIdx.y >= 4) return;
        sgemm_body(pE, l1w + (size_t)D_ * D_, l1b, pEE, E_, D_, D_);
    }
}

// ---------------- main kernel: mma.sync m16n8k16 fp16 ----------------
// CTA = (2 p, 128 e, 128 n). 512 threads = 16 warps = (2p x 4e x 2n),
// warp tile 32e x 64n. A = fp16(relu(ee+pp)) built in registers per k16.
// grid = 4096: bid = pg*8 + eh*4 + nt
#define EES 40   // ee smem row stride (floats): bank-perfect paired LDS.64

__global__ __launch_bounds__(512, 1) void big_kernel(const float* __restrict__ pp,
                                                     const float* __restrict__ ee,
                                                     const __half* __restrict__ wth,
                                                     const float* __restrict__ bias,
                                                     float* __restrict__ out) {
    __shared__ float ee_s[128 * EES];          // 20480 B
    __shared__ __half b_s[2][128][16];         // 8192 B: [k16-sub][n-row][perm halfs]
    __shared__ float pp_s[2 * 512];
    __shared__ float bias_s[128];

    const int tid = threadIdx.x;
    const int bid = blockIdx.x;
    const int nt = bid & 3, eh = (bid >> 2) & 1, pg = bid >> 3;
    const int n0 = nt * 128, e0 = eh * 128, p0 = pg * 2;

    const int wid = tid >> 5, lane = tid & 31;
    const int g = lane >> 2, t = lane & 3;
    const int p_i = wid >> 3;               // 0..1
    const int e_w = ((wid >> 1) & 3) * 32;  // 0,32,64,96
    const int n_w = (wid & 1) * 64;         // 0,64

    // one-time loads
    for (int i = tid; i < 1024; i += 512)
        pp_s[i] = pp[(size_t)(p0 + (i >> 9)) * 512 + (i & 511)];
    if (tid < 128) bias_s[tid] = (n0 + tid < OUT_) ? bias[n0 + tid] : 0.0f;

    float acc[2][8][4];
#pragma unroll
    for (int mi = 0; mi < 2; mi++)
#pragma unroll
        for (int ni = 0; ni < 8; ni++)
#pragma unroll
            for (int j = 0; j < 4; j++) acc[mi][ni][j] = 0.0f;

    // staging: row = tid>>2 (0..127), seg = tid&3 (8 floats / 8 halfs each)
    const int row = tid >> 2, seg = tid & 3;
    const float* ee_g = ee + (size_t)(e0 + row) * 512 + seg * 8;
    const __half* wt_g = wth + (size_t)(n0 + row) * 512 + seg * 8;
    const int eso = row * EES + seg * 8;
    const int bsub = seg >> 1, bcol = (seg & 1) * 8;

    float4 re0 = *(const float4*)(ee_g);
    float4 re1 = *(const float4*)(ee_g + 4);
    uint4 rb = *(const uint4*)(wt_g);

#pragma unroll 1
    for (int c = 0; c < 16; ++c) {
        __syncthreads();  // previous chunk consumed (1st: pp_s/bias_s ready)
        *(float4*)&ee_s[eso] = re0;
        *(float4*)&ee_s[eso + 4] = re1;
        *(uint4*)&b_s[bsub][row][bcol] = rb;
        __syncthreads();

        if (c < 15) {  // prefetch next chunk during compute
            int k0 = (c + 1) * 32;
            re0 = *(const float4*)(ee_g + k0);
            re1 = *(const float4*)(ee_g + k0 + 4);
            rb = *(const uint4*)(wt_g + k0);
        }

        const float* ppc = &pp_s[p_i * 512 + c * 32];
#pragma unroll
        for (int sub = 0; sub < 2; ++sub) {
            const int kk = sub * 16;
            const float2 pA = *(const float2*)&ppc[kk + 2 * t];
            const float2 pB = *(const float2*)&ppc[kk + 2 * t + 8];
            uint32_t a[2][4];
#pragma unroll
            for (int mi = 0; mi < 2; ++mi) {
                const float* er0 = &ee_s[(e_w + mi * 16 + g) * EES + kk];
                const float* er1 = er0 + 8 * EES;
                const float2 x0 = *(const float2*)&er0[2 * t];
                const float2 x1 = *(const float2*)&er1[2 * t];
                const float2 x2 = *(const float2*)&er0[2 * t + 8];
                const float2 x3 = *(const float2*)&er1[2 * t + 8];
                a[mi][0] = pack_relu_h2(x0.x + pA.x, x0.y + pA.y);
                a[mi][1] = pack_relu_h2(x1.x + pA.x, x1.y + pA.y);
                a[mi][2] = pack_relu_h2(x2.x + pB.x, x2.y + pB.y);
                a[mi][3] = pack_relu_h2(x3.x + pB.x, x3.y + pB.y);
            }
#pragma unroll
            for (int ni = 0; ni < 8; ++ni) {
                const uint2 bv = *(const uint2*)&b_s[sub][n_w + ni * 8 + g][4 * t];
                uint32_t b[2] = {bv.x, bv.y};
                mma16(acc[0][ni], a[0], b);
                mma16(acc[1][ni], a[1], b);
            }
        }
    }

    // epilogue: bias + relu, float2 stores (rows = 2000B -> 8B aligned)
    const int ebase = e0 + e_w + g;
    const size_t prow = (size_t)(p0 + p_i) * E_;
#pragma unroll
    for (int mi = 0; mi < 2; ++mi) {
        float* r0 = out + (prow + ebase + mi * 16) * OUT_;
#pragma unroll
        for (int ni = 0; ni < 8; ++ni) {
            const int ncl = n_w + ni * 8 + 2 * t;  // even, 0..126
            const int n = n0 + ncl;
            if (n < OUT_) {
                const float bz0 = bias_s[ncl], bz1 = bias_s[ncl + 1];
                float2 v0, v1;
                v0.x = fmaxf(acc[mi][ni][0] + bz0, 0.0f);
                v0.y = fmaxf(acc[mi][ni][1] + bz1, 0.0f);
                v1.x = fmaxf(acc[mi][ni][2] + bz0, 0.0f);
                v1.y = fmaxf(acc[mi][ni][3] + bz1, 0.0f);
                *(float2*)(r0 + n) = v0;
                *(float2*)(r0 + 8 * OUT_ + n) = v1;
            }
        }
    }
}

// ---------------- launch ----------------
extern "C" void kernel_launch(void* const* d_in, const int* in_sizes, int n_in,
                              void* d_out, int out_size) {
    const float* post  = (const float*)d_in[0];
    const float* emoji = (const float*)d_in[1];
    const float* k1_w  = (const float*)d_in[2];
    const float* k1_b  = (const float*)d_in[3];
    const float* k2_w  = (const float*)d_in[4];
    const float* k2_b  = (const float*)d_in[5];
    const float* l1_w  = (const float*)d_in[6];
    const float* l1_b  = (const float*)d_in[7];
    const float* l2_w  = (const float*)d_in[8];
    const float* l2_b  = (const float*)d_in[9];
    float* out = (float*)d_out;

    float *pP, *pE, *pPP, *pEE;
    __half* pWT;
    cudaGetSymbolAddress((void**)&pP, g_p);
    cudaGetSymbolAddress((void**)&pE, g_e);
    cudaGetSymbolAddress((void**)&pPP, g_pp);
    cudaGetSymbolAddress((void**)&pEE, g_ee);
    cudaGetSymbolAddress((void**)&pWT, g_wth);

    // launch 1: p = post@k1_w + k1_b ; e = emoji@k2_w + k2_b ; Wt prep
    fused1<<<dim3(8, 16, 3), 256>>>(post, k1_w, k1_b, emoji, k2_w, k2_b, l2_w,
                                    pP, pE, pWT);
    // launch 2: pp = p@l1_w[:D] ; ee = e@l1_w[D:] + l1_b
    fused2<<<dim3(8, 16, 2), 256>>>(pP, pE, l1_w, l1_b, pPP, pEE);
    // main pairwise GEMM
    big_kernel<<<4096, 512>>>(pPP, pEE, pWT, l2_b, out);
}

// round 5
// speedup vs baseline: 2.3631x; 1.1694x over previous
#include <cuda_runtime.h>
#include <cuda_fp16.h>
#include <cstdint>

#define D_ 512
#define P_ 1024
#define E_ 256
#define OUT_ 500

// ---------------- device scratch ----------------
__device__ float g_p[P_ * D_];
__device__ float g_e[E_ * D_];
__device__ float g_pp[P_ * D_];   // fp32, k-permuted within each 16-block
__device__ float g_ee[E_ * D_];   // fp32, k-permuted within each 16-block
__device__ __half g_wth[512 * 512]; // [n][k] fp16, n padded to 512, k-permuted

// k-permutation within a 16-block: stored[4t + 2h + l] = orig[2t + 8h + l]
// -> one 8B/16B read at t*{8,16} yields exactly the m16n8k16 fragment k-pairs.

// ---------------- helpers ----------------
__device__ __forceinline__ uint32_t smem_u32(const void* p) {
    uint32_t a;
    asm("{ .reg .u64 t; cvta.to.shared.u64 t, %1; cvt.u32.u64 %0, t; }" : "=r"(a) : "l"(p));
    return a;
}
__device__ __forceinline__ void mma16(float* d, const uint32_t* a, const uint32_t* b) {
    asm volatile(
        "mma.sync.aligned.m16n8k16.row.col.f32.f16.f16.f32 "
        "{%0,%1,%2,%3}, {%4,%5,%6,%7}, {%8,%9}, {%0,%1,%2,%3};"
        : "+f"(d[0]), "+f"(d[1]), "+f"(d[2]), "+f"(d[3])
        : "r"(a[0]), "r"(a[1]), "r"(a[2]), "r"(a[3]), "r"(b[0]), "r"(b[1]));
}
__device__ __forceinline__ uint32_t pack_relu_h2(float lo, float hi) {
    __half2 h = __floats2half2_rn(fmaxf(lo, 0.0f), fmaxf(hi, 0.0f));
    return *(uint32_t*)&h;
}
__device__ __forceinline__ void cp16(uint32_t s, const void* g) {
    asm volatile("cp.async.cg.shared.global [%0], [%1], 16;" :: "r"(s), "l"(g));
}
#define CP_COMMIT() asm volatile("cp.async.commit_group;" ::: "memory")
#define CP_WAIT1()  asm volatile("cp.async.wait_group 1;" ::: "memory")

// ---------------- fp32 SGEMM body (+optional permuted write) ----------------
template <bool PERM>
__device__ __forceinline__ void sgemm_body(const float* __restrict__ A,
                                           const float* __restrict__ B,
                                           const float* __restrict__ bias,
                                           float* __restrict__ C,
                                           int M, int N, int K) {
    __shared__ float As[16][64];
    __shared__ float Bs[16][64];
    int tid = threadIdx.x;
    int bm = blockIdx.y * 64, bn = blockIdx.x * 64;
    int tx = tid & 15, ty = tid >> 4;
    float acc[4][4];
#pragma unroll
    for (int i = 0; i < 4; i++)
#pragma unroll
        for (int j = 0; j < 4; j++) acc[i][j] = 0.0f;

    int ar = tid >> 2, ak = (tid & 3) * 4;
    int br = tid >> 4, bc = (tid & 15) * 4;
    for (int k0 = 0; k0 < K; k0 += 16) {
        float4 a = *(const float4*)(A + (size_t)(bm + ar) * K + k0 + ak);
        As[ak + 0][ar] = a.x; As[ak + 1][ar] = a.y;
        As[ak + 2][ar] = a.z; As[ak + 3][ar] = a.w;
        *(float4*)&Bs[br][bc] = *(const float4*)(B + (size_t)(k0 + br) * N + bn + bc);
        __syncthreads();
#pragma unroll
        for (int kk = 0; kk < 16; kk++) {
            float4 av = *(const float4*)&As[kk][ty * 4];
            float4 bv = *(const float4*)&Bs[kk][tx * 4];
            acc[0][0] += av.x * bv.x; acc[0][1] += av.x * bv.y;
            acc[0][2] += av.x * bv.z; acc[0][3] += av.x * bv.w;
            acc[1][0] += av.y * bv.x; acc[1][1] += av.y * bv.y;
            acc[1][2] += av.y * bv.z; acc[1][3] += av.y * bv.w;
            acc[2][0] += av.z * bv.x; acc[2][1] += av.z * bv.y;
            acc[2][2] += av.z * bv.z; acc[2][3] += av.z * bv.w;
            acc[3][0] += av.w * bv.x; acc[3][1] += av.w * bv.y;
            acc[3][2] += av.w * bv.z; acc[3][3] += av.w * bv.w;
        }
        __syncthreads();
    }
    int col = bn + tx * 4;
    float4 bb = make_float4(0.f, 0.f, 0.f, 0.f);
    if (bias) bb = *(const float4*)(bias + col);
#pragma unroll
    for (int i = 0; i < 4; i++) {
        float v[4];
        v[0] = acc[i][0] + bb.x; v[1] = acc[i][1] + bb.y;
        v[2] = acc[i][2] + bb.z; v[3] = acc[i][3] + bb.w;
        float* crow = C + (size_t)(bm + ty * 4 + i) * N;
        if (!PERM) {
            float4 q = {v[0], v[1], v[2], v[3]};
            *(float4*)(crow + col) = q;
        } else {
#pragma unroll
            for (int jc = 0; jc < 4; jc++) {
                int ks = col + jc;
                int blk = ks >> 4, kk = ks & 15;
                int j = ((kk & 7) >> 1) * 4 + ((kk >> 3) & 1) * 2 + (kk & 1);
                crow[blk * 16 + j] = v[jc];
            }
        }
    }
}

// ---------------- fused launch 1: p-gemm, e-gemm, Wt prep ----------------
__global__ __launch_bounds__(256) void fused1(const float* __restrict__ post,
                                              const float* __restrict__ k1w,
                                              const float* __restrict__ k1b,
                                              const float* __restrict__ emoji,
                                              const float* __restrict__ k2w,
                                              const float* __restrict__ k2b,
                                              const float* __restrict__ l2w,
                                              float* __restrict__ pP,
                                              float* __restrict__ pE,
                                              __half* __restrict__ wth) {
    int z = blockIdx.z;
    if (z == 2) {
        int b = blockIdx.y * gridDim.x + blockIdx.x;  // 0..127
        int base = b * 2048;
#pragma unroll
        for (int it = 0; it < 8; it++) {
            int idx = base + it * 256 + threadIdx.x;
            int n = idx >> 9, j = idx & 511;
            int k16 = j >> 4, jj = j & 15;
            int t = jj >> 2, r = jj & 3;
            int ks = k16 * 16 + 2 * t + ((r >> 1) << 3) + (r & 1);
            float v = (n < OUT_) ? l2w[ks * OUT_ + n] : 0.0f;
            wth[idx] = __float2half_rn(v);
        }
        return;
    }
    if (z == 0) {
        sgemm_body<false>(post, k1w, k1b, pP, P_, D_, D_);
    } else {
        if (blockIdx.y >= 4) return;
        sgemm_body<false>(emoji, k2w, k2b, pE, E_, D_, D_);
    }
}

// ---------------- fused launch 2: pp-gemm, ee-gemm (permuted fp32 out) -------
__global__ __launch_bounds__(256) void fused2(const float* __restrict__ pP,
                                              const float* __restrict__ pE,
                                              const float* __restrict__ l1w,
                                              const float* __restrict__ l1b,
                                              float* __restrict__ pPP,
                                              float* __restrict__ pEE) {
    if (blockIdx.z == 0) {
        sgemm_body<true>(pP, l1w, nullptr, pPP, P_, D_, D_);
    } else {
        if (blockIdx.y >= 4) return;
        sgemm_body<true>(pE, l1w + (size_t)D_ * D_, l1b, pEE, E_, D_, D_);
    }
}

// ---------------- main kernel ----------------
// CTA = (2p, 128e, 128n), 512 thr = 16 warps = 2p x 8 e-groups(16 rows), full n.
// 3-stage cp.async pipeline, 1 sync/chunk. SMEM XOR-swizzled, conflict-free.
#define EE_B 16384u        // 128 rows x 128B per buffer
#define B_B  8192u         // 128 rows x 64B per buffer
#define OFF_B  (3 * EE_B)                 // 49152
#define OFF_PP (OFF_B + 3 * B_B)          // 73728
#define OFF_BI (OFF_PP + 4096u)           // 77824
#define DYN_SMEM (OFF_BI + 512u)          // 78336

__global__ __launch_bounds__(512, 1) void big_kernel(const float* __restrict__ pp,
                                                     const float* __restrict__ ee,
                                                     const __half* __restrict__ wth,
                                                     const float* __restrict__ bias,
                                                     float* __restrict__ out) {
    extern __shared__ char dsm[];
    const uint32_t sbu = smem_u32(dsm);

    const int tid = threadIdx.x;
    const int bid = blockIdx.x;
    const int nt = bid & 3, eh = (bid >> 2) & 1, pg = bid >> 3;
    const int n0 = nt * 128, e0 = eh * 128, p0 = pg * 2;

    const int wid = tid >> 5, lane = tid & 31;
    const int g = lane >> 2, t = lane & 3;
    const int p_i = wid >> 3;        // 0..1
    const int e_g = wid & 7;         // e-group (16 rows each)

    // ---- staging source pointers (per-thread fixed row) ----
    const int srow = tid >> 2;                       // 0..127
    const int es2 = (tid & 3) * 2;                   // ee segs pair
    const int bs  = tid & 3;                         // b seg
    const char* ee_src = (const char*)(ee + (size_t)(e0 + srow) * 512);
    const char* wt_src = (const char*)(wth + (size_t)(n0 + srow) * 512);
    const uint32_t ee_dst_row = srow * 128u;
    const uint32_t b_dst_row  = srow * 64u;
    const uint32_t eswz_w = (uint32_t)((srow & 1) * 64);
    const uint32_t bswz_w = (uint32_t)(((srow >> 1) & 1) * 32);
    const uint32_t ee_d0 = ee_dst_row + (((uint32_t)es2 * 16u) ^ eswz_w);
    const uint32_t ee_d1 = ee_dst_row + (((uint32_t)(es2 + 1) * 16u) ^ eswz_w);
    const uint32_t b_d   = b_dst_row + (((uint32_t)bs * 16u) ^ bswz_w);

#define ISSUE(c)                                                        \
    do {                                                                \
        uint32_t _eb = sbu + ((c) % 3) * EE_B;                          \
        uint32_t _bb = sbu + OFF_B + ((c) % 3) * B_B;                   \
        const char* _es = ee_src + (c) * 128;                           \
        cp16(_eb + ee_d0, _es + es2 * 16);                              \
        cp16(_eb + ee_d1, _es + es2 * 16 + 16);                         \
        cp16(_bb + b_d, wt_src + (c) * 64 + bs * 16);                   \
    } while (0)

    // prologue: chunks 0,1 in flight
    ISSUE(0); CP_COMMIT();
    ISSUE(1); CP_COMMIT();

    // pp (fp32 permuted) + bias to smem
    float* pp_s = (float*)(dsm + OFF_PP);
    float* bias_s = (float*)(dsm + OFF_BI);
    for (int i = tid; i < 1024; i += 512)
        pp_s[i] = pp[(size_t)(p0 + (i >> 9)) * 512 + (i & 511)];
    if (tid < 128) bias_s[tid] = (n0 + tid < OUT_) ? bias[n0 + tid] : 0.0f;

    float acc[16][4];
#pragma unroll
    for (int ni = 0; ni < 16; ni++)
#pragma unroll
        for (int j = 0; j < 4; j++) acc[ni][j] = 0.0f;

    // read-side constants
    const int r0 = e_g * 16 + g;               // A row (and r0+8)
    const uint32_t eswz_r = (uint32_t)((g & 1) * 64);
    const uint32_t bswz_r = (uint32_t)(((g >> 1) & 1) * 32);
    const uint32_t aoff[2] = {
        (((uint32_t)(0 * 64 + t * 16)) ^ eswz_r),
        (((uint32_t)(1 * 64 + t * 16)) ^ eswz_r)};
    const uint32_t boff[2] = {
        (((uint32_t)(0 * 32 + t * 8)) ^ bswz_r),
        (((uint32_t)(1 * 32 + t * 8)) ^ bswz_r)};

#pragma unroll 1
    for (int c = 0; c < 16; ++c) {
        CP_WAIT1();
        __syncthreads();
        if (c + 2 < 16) { ISSUE(c + 2); CP_COMMIT(); }
        else { CP_COMMIT(); }  // keep group accounting so WAIT1 forces chunk c

        const char* eb = dsm + (c % 3) * EE_B;
        const char* bb = dsm + OFF_B + (c % 3) * B_B;
        const float* ppc = pp_s + p_i * 512 + c * 32;

#pragma unroll
        for (int sub = 0; sub < 2; ++sub) {
            const float4 pv = *(const float4*)(ppc + sub * 16 + t * 4);
            const float4 v0 = *(const float4*)(eb + r0 * 128 + aoff[sub]);
            const float4 v1 = *(const float4*)(eb + (r0 + 8) * 128 + aoff[sub]);
            uint32_t a[4];
            a[0] = pack_relu_h2(v0.x + pv.x, v0.y + pv.y);
            a[1] = pack_relu_h2(v1.x + pv.x, v1.y + pv.y);
            a[2] = pack_relu_h2(v0.z + pv.z, v0.w + pv.w);
            a[3] = pack_relu_h2(v1.z + pv.z, v1.w + pv.w);
#pragma unroll
            for (int ni = 0; ni < 16; ++ni) {
                const uint2 bv =
                    *(const uint2*)(bb + (ni * 8 + g) * 64 + boff[sub]);
                uint32_t b2[2] = {bv.x, bv.y};
                mma16(acc[ni], a, b2);
            }
        }
    }

    // ---- epilogue: bias + relu, float2 stores ----
    const int er0 = e0 + e_g * 16 + g;
    const size_t prow = (size_t)(p0 + p_i) * E_;
    float* o0 = out + (prow + er0) * OUT_;
    float* o1 = out + (prow + er0 + 8) * OUT_;
#pragma unroll
    for (int ni = 0; ni < 16; ++ni) {
        const int ncl = ni * 8 + 2 * t;       // even
        const int n = n0 + ncl;
        if (n < OUT_) {
            const float bz0 = bias_s[ncl], bz1 = bias_s[ncl + 1];
            float2 w0, w1;
            w0.x = fmaxf(acc[ni][0] + bz0, 0.0f);
            w0.y = fmaxf(acc[ni][1] + bz1, 0.0f);
            w1.x = fmaxf(acc[ni][2] + bz0, 0.0f);
            w1.y = fmaxf(acc[ni][3] + bz1, 0.0f);
            *(float2*)(o0 + n) = w0;
            *(float2*)(o1 + n) = w1;
        }
    }
#undef ISSUE
}

// ---------------- launch ----------------
extern "C" void kernel_launch(void* const* d_in, const int* in_sizes, int n_in,
                              void* d_out, int out_size) {
    const float* post  = (const float*)d_in[0];
    const float* emoji = (const float*)d_in[1];
    const float* k1_w  = (const float*)d_in[2];
    const float* k1_b  = (const float*)d_in[3];
    const float* k2_w  = (const float*)d_in[4];
    const float* k2_b  = (const float*)d_in[5];
    const float* l1_w  = (const float*)d_in[6];
    const float* l1_b  = (const float*)d_in[7];
    const float* l2_w  = (const float*)d_in[8];
    const float* l2_b  = (const float*)d_in[9];
    float* out = (float*)d_out;

    float *pP, *pE, *pPP, *pEE;
    __half* pWT;
    cudaGetSymbolAddress((void**)&pP, g_p);
    cudaGetSymbolAddress((void**)&pE, g_e);
    cudaGetSymbolAddress((void**)&pPP, g_pp);
    cudaGetSymbolAddress((void**)&pEE, g_ee);
    cudaGetSymbolAddress((void**)&pWT, g_wth);

    cudaFuncSetAttribute(big_kernel, cudaFuncAttributeMaxDynamicSharedMemorySize,
                         DYN_SMEM);

    fused1<<<dim3(8, 16, 3), 256>>>(post, k1_w, k1_b, emoji, k2_w, k2_b, l2_w,
                                    pP, pE, pWT);
    fused2<<<dim3(8, 16, 2), 256>>>(pP, pE, l1_w, l1_b, pPP, pEE);
    big_kernel<<<4096, 512, DYN_SMEM>>>(pPP, pEE, pWT, l2_b, out);
}

// round 6
// speedup vs baseline: 2.5873x; 1.0949x over previous
#include <cuda_runtime.h>
#include <cuda_fp16.h>
#include <cstdint>

#define D_ 512
#define P_ 1024
#define E_ 256
#define OUT_ 500

// ---------------- device scratch ----------------
// fp16 operands, all [row][k] with k permuted within each 16-block:
// stored[4t + 2h + l] = orig[2t + 8h + l]  (one 8B read at t*8 = an mma k-pair set)
__device__ __half g_posth[P_ * D_];
__device__ __half g_emojih[E_ * D_];
__device__ __half g_k1wh[512 * 512];   // [n][k] from k1_w[k][n]
__device__ __half g_k2wh[512 * 512];
__device__ __half g_l1ph[512 * 512];   // l1_w[:512] transposed
__device__ __half g_l1eh[512 * 512];   // l1_w[512:] transposed
__device__ __half g_ph[P_ * 512];      // p = post@k1+b, fp16, k-permuted
__device__ __half g_eh[E_ * 512];      // e
__device__ float g_pp[P_ * D_];        // fp32, k-permuted
__device__ float g_ee[E_ * D_];        // fp32, k-permuted (+l1_b)
__device__ __half g_wth[512 * 512];    // l2_w transposed, fp16, k-permuted

// ---------------- helpers ----------------
__device__ __forceinline__ uint32_t smem_u32(const void* p) {
    uint32_t a;
    asm("{ .reg .u64 t; cvta.to.shared.u64 t, %1; cvt.u32.u64 %0, t; }" : "=r"(a) : "l"(p));
    return a;
}
__device__ __forceinline__ void mma16(float* d, const uint32_t* a, const uint32_t* b) {
    asm volatile(
        "mma.sync.aligned.m16n8k16.row.col.f32.f16.f16.f32 "
        "{%0,%1,%2,%3}, {%4,%5,%6,%7}, {%8,%9}, {%0,%1,%2,%3};"
        : "+f"(d[0]), "+f"(d[1]), "+f"(d[2]), "+f"(d[3])
        : "r"(a[0]), "r"(a[1]), "r"(a[2]), "r"(a[3]), "r"(b[0]), "r"(b[1]));
}
__device__ __forceinline__ uint32_t pack_relu_h2(float lo, float hi) {
    __half2 h = __floats2half2_rn(fmaxf(lo, 0.0f), fmaxf(hi, 0.0f));
    return *(uint32_t*)&h;
}
__device__ __forceinline__ uint32_t pack_h2(float lo, float hi) {
    __half2 h = __floats2half2_rn(lo, hi);
    return *(uint32_t*)&h;
}
__device__ __forceinline__ void cp16(uint32_t s, const void* g) {
    asm volatile("cp.async.cg.shared.global [%0], [%1], 16;" :: "r"(s), "l"(g));
}
#define CP_COMMIT() asm volatile("cp.async.commit_group;" ::: "memory")
#define CP_WAIT1()  asm volatile("cp.async.wait_group 1;" ::: "memory")

// permuted k -> original k within 16-blocks
__device__ __forceinline__ int kperm_src(int kp) {
    int j = kp & 15, t = j >> 2, r = j & 3;
    return (kp & ~15) + 2 * t + ((r >> 1) << 3) + (r & 1);
}

// ---------------- prep: all fp16 converts / transposes ----------------
// segments (dest-linear): post_h 524288 | emoji_h 131072 | k1wh 262144 |
// k2wh 262144 | l1ph 262144 | l1eh 262144 | wth 262144  = 1966080 = 960*2048
__global__ __launch_bounds__(256) void prep(const float* __restrict__ post,
                                            const float* __restrict__ emoji,
                                            const float* __restrict__ k1w,
                                            const float* __restrict__ k2w,
                                            const float* __restrict__ l1w,
                                            const float* __restrict__ l2w,
                                            __half* __restrict__ post_h,
                                            __half* __restrict__ emoji_h,
                                            __half* __restrict__ k1wh,
                                            __half* __restrict__ k2wh,
                                            __half* __restrict__ l1ph,
                                            __half* __restrict__ l1eh,
                                            __half* __restrict__ wth) {
#pragma unroll
    for (int it = 0; it < 8; it++) {
        int gidx = blockIdx.x * 2048 + it * 256 + threadIdx.x;
        int u = gidx;
        if (u < 524288) {
            int m = u >> 9, ks = kperm_src(u & 511);
            post_h[u] = __float2half_rn(post[m * 512 + ks]);
            continue;
        }
        u -= 524288;
        if (u < 131072) {
            int m = u >> 9, ks = kperm_src(u & 511);
            emoji_h[u] = __float2half_rn(emoji[m * 512 + ks]);
            continue;
        }
        u -= 131072;
        if (u < 262144) {
            int n = u >> 9, ks = kperm_src(u & 511);
            k1wh[u] = __float2half_rn(k1w[ks * 512 + n]);
            continue;
        }
        u -= 262144;
        if (u < 262144) {
            int n = u >> 9, ks = kperm_src(u & 511);
            k2wh[u] = __float2half_rn(k2w[ks * 512 + n]);
            continue;
        }
        u -= 262144;
        if (u < 262144) {
            int n = u >> 9, ks = kperm_src(u & 511);
            l1ph[u] = __float2half_rn(l1w[ks * 512 + n]);
            continue;
        }
        u -= 262144;
        if (u < 262144) {
            int n = u >> 9, ks = kperm_src(u & 511);
            l1eh[u] = __float2half_rn(l1w[(512 + ks) * 512 + n]);
            continue;
        }
        u -= 262144;
        {
            int n = u >> 9, ks = kperm_src(u & 511);
            float v = (n < OUT_) ? l2w[ks * OUT_ + n] : 0.0f;
            wth[u] = __float2half_rn(v);
        }
    }
}

// ---------------- fp16 MMA GEMM for the small chain ----------------
// out[m][n] = sum_k A[m][k]*B[n][k] (+bias[n]); K=512 fixed.
// CTA 64m x 64n, 256 thr = 8 warps = 4m-groups x 2n-groups; warp 16m x 32n.
// BK=32, 3-stage cp.async. SMEM rows 96B (64B data + 32B pad) = conflict-free.
// OUT16: write fp16 k-permuted (for next-stage A); else fp32 k-permuted.
// grid.y: [0,16) -> job0 (M=1024); [16,20) -> job1 (M=256).
#define GH_BUF 12288   // 6144 A + 6144 B per stage

template <bool OUT16>
__global__ __launch_bounds__(256) void gemm_h(const __half* __restrict__ A0,
                                              const __half* __restrict__ B0,
                                              const float* __restrict__ bias0,
                                              void* __restrict__ out0,
                                              const __half* __restrict__ A1,
                                              const __half* __restrict__ B1,
                                              const float* __restrict__ bias1,
                                              void* __restrict__ out1) {
    __shared__ __align__(16) char sm[3 * GH_BUF];
    const uint32_t sbu = smem_u32(sm);

    const int tid = threadIdx.x;
    const __half* A;
    const __half* B;
    const float* bias;
    void* out;
    int mrow0;
    if (blockIdx.y < 16) {
        A = A0; B = B0; bias = bias0; out = out0; mrow0 = blockIdx.y * 64;
    } else {
        A = A1; B = B1; bias = bias1; out = out1; mrow0 = (blockIdx.y - 16) * 64;
    }
    const int ncol0 = blockIdx.x * 64;

    const int wid = tid >> 5, lane = tid & 31;
    const int g = lane >> 2, t = lane & 3;
    const int mgrp = wid >> 1, nw = (wid & 1) * 32;

    // staging: row = tid>>2 (0..63), seg = tid&3
    const int srow = tid >> 2, seg = tid & 3;
    const char* a_src = (const char*)(A + (size_t)(mrow0 + srow) * 512);
    const char* b_src = (const char*)(B + (size_t)(ncol0 + srow) * 512);
    const uint32_t a_d = srow * 96u + seg * 16u;
    const uint32_t b_d = 6144u + srow * 96u + seg * 16u;

#define GH_ISSUE(c)                                             \
    do {                                                        \
        uint32_t _b = sbu + ((c) % 3) * GH_BUF;                 \
        cp16(_b + a_d, a_src + (c) * 64 + seg * 16);            \
        cp16(_b + b_d, b_src + (c) * 64 + seg * 16);            \
    } while (0)

    GH_ISSUE(0); CP_COMMIT();
    GH_ISSUE(1); CP_COMMIT();

    float acc[4][4];
#pragma unroll
    for (int ni = 0; ni < 4; ni++)
#pragma unroll
        for (int j = 0; j < 4; j++) acc[ni][j] = 0.0f;

    const int arow = mgrp * 16 + g;

#pragma unroll 1
    for (int c = 0; c < 16; ++c) {
        CP_WAIT1();
        __syncthreads();
        if (c + 2 < 16) { GH_ISSUE(c + 2); CP_COMMIT(); }
        else { CP_COMMIT(); }

        const char* ab = sm + (c % 3) * GH_BUF;
        const char* bb = ab + 6144;
#pragma unroll
        for (int sub = 0; sub < 2; ++sub) {
            const uint32_t ko = sub * 32 + t * 8;
            const uint2 alo = *(const uint2*)(ab + arow * 96 + ko);
            const uint2 ahi = *(const uint2*)(ab + (arow + 8) * 96 + ko);
            uint32_t a[4] = {alo.x, ahi.x, alo.y, ahi.y};
#pragma unroll
            for (int ni = 0; ni < 4; ++ni) {
                const uint2 bv = *(const uint2*)(bb + (nw + ni * 8 + g) * 96 + ko);
                uint32_t b2[2] = {bv.x, bv.y};
                mma16(acc[ni], a, b2);
            }
        }
    }

    // epilogue: permuted writes (+bias)
    const int m0 = mrow0 + mgrp * 16 + g;
#pragma unroll
    for (int ni = 0; ni < 4; ++ni) {
        const int ncol = ncol0 + nw + ni * 8;
        const int off = (ncol >> 4) * 16 + 4 * t + 2 * (ni & 1);
        const float b0v = bias ? bias[ncol + 2 * t] : 0.0f;
        const float b1v = bias ? bias[ncol + 2 * t + 1] : 0.0f;
        if (OUT16) {
            __half* o = (__half*)out;
            *(uint32_t*)(o + (size_t)m0 * 512 + off) =
                pack_h2(acc[ni][0] + b0v, acc[ni][1] + b1v);
            *(uint32_t*)(o + (size_t)(m0 + 8) * 512 + off) =
                pack_h2(acc[ni][2] + b0v, acc[ni][3] + b1v);
        } else {
            float* o = (float*)out;
            float2 w0 = {acc[ni][0] + b0v, acc[ni][1] + b1v};
            float2 w1 = {acc[ni][2] + b0v, acc[ni][3] + b1v};
            *(float2*)(o + (size_t)m0 * 512 + off) = w0;
            *(float2*)(o + (size_t)(m0 + 8) * 512 + off) = w1;
        }
    }
#undef GH_ISSUE
}

// ---------------- main kernel (unchanged from R5) ----------------
#define EE_B 16384u
#define B_B  8192u
#define OFF_B  (3 * EE_B)
#define OFF_PP (OFF_B + 3 * B_B)
#define OFF_BI (OFF_PP + 4096u)
#define DYN_SMEM (OFF_BI + 512u)

__global__ __launch_bounds__(512, 1) void big_kernel(const float* __restrict__ pp,
                                                     const float* __restrict__ ee,
                                                     const __half* __restrict__ wth,
                                                     const float* __restrict__ bias,
                                                     float* __restrict__ out) {
    extern __shared__ char dsm[];
    const uint32_t sbu = smem_u32(dsm);

    const int tid = threadIdx.x;
    const int bid = blockIdx.x;
    const int nt = bid & 3, eh = (bid >> 2) & 1, pg = bid >> 3;
    const int n0 = nt * 128, e0 = eh * 128, p0 = pg * 2;

    const int wid = tid >> 5, lane = tid & 31;
    const int g = lane >> 2, t = lane & 3;
    const int p_i = wid >> 3;
    const int e_g = wid & 7;

    const int srow = tid >> 2;
    const int es2 = (tid & 3) * 2;
    const int bs  = tid & 3;
    const char* ee_src = (const char*)(ee + (size_t)(e0 + srow) * 512);
    const char* wt_src = (const char*)(wth + (size_t)(n0 + srow) * 512);
    const uint32_t ee_dst_row = srow * 128u;
    const uint32_t b_dst_row  = srow * 64u;
    const uint32_t eswz_w = (uint32_t)((srow & 1) * 64);
    const uint32_t bswz_w = (uint32_t)(((srow >> 1) & 1) * 32);
    const uint32_t ee_d0 = ee_dst_row + (((uint32_t)es2 * 16u) ^ eswz_w);
    const uint32_t ee_d1 = ee_dst_row + (((uint32_t)(es2 + 1) * 16u) ^ eswz_w);
    const uint32_t b_d   = b_dst_row + (((uint32_t)bs * 16u) ^ bswz_w);

#define ISSUE(c)                                                        \
    do {                                                                \
        uint32_t _eb = sbu + ((c) % 3) * EE_B;                          \
        uint32_t _bb = sbu + OFF_B + ((c) % 3) * B_B;                   \
        const char* _es = ee_src + (c) * 128;                           \
        cp16(_eb + ee_d0, _es + es2 * 16);                              \
        cp16(_eb + ee_d1, _es + es2 * 16 + 16);                         \
        cp16(_bb + b_d, wt_src + (c) * 64 + bs * 16);                   \
    } while (0)

    ISSUE(0); CP_COMMIT();
    ISSUE(1); CP_COMMIT();

    float* pp_s = (float*)(dsm + OFF_PP);
    float* bias_s = (float*)(dsm + OFF_BI);
    for (int i = tid; i < 1024; i += 512)
        pp_s[i] = pp[(size_t)(p0 + (i >> 9)) * 512 + (i & 511)];
    if (tid < 128) bias_s[tid] = (n0 + tid < OUT_) ? bias[n0 + tid] : 0.0f;

    float acc[16][4];
#pragma unroll
    for (int ni = 0; ni < 16; ni++)
#pragma unroll
        for (int j = 0; j < 4; j++) acc[ni][j] = 0.0f;

    const int r0 = e_g * 16 + g;
    const uint32_t eswz_r = (uint32_t)((g & 1) * 64);
    const uint32_t bswz_r = (uint32_t)(((g >> 1) & 1) * 32);
    const uint32_t aoff[2] = {
        (((uint32_t)(0 * 64 + t * 16)) ^ eswz_r),
        (((uint32_t)(1 * 64 + t * 16)) ^ eswz_r)};
    const uint32_t boff[2] = {
        (((uint32_t)(0 * 32 + t * 8)) ^ bswz_r),
        (((uint32_t)(1 * 32 + t * 8)) ^ bswz_r)};

#pragma unroll 1
    for (int c = 0; c < 16; ++c) {
        CP_WAIT1();
        __syncthreads();
        if (c + 2 < 16) { ISSUE(c + 2); CP_COMMIT(); }
        else { CP_COMMIT(); }

        const char* eb = dsm + (c % 3) * EE_B;
        const char* bb = dsm + OFF_B + (c % 3) * B_B;
        const float* ppc = pp_s + p_i * 512 + c * 32;

#pragma unroll
        for (int sub = 0; sub < 2; ++sub) {
            const float4 pv = *(const float4*)(ppc + sub * 16 + t * 4);
            const float4 v0 = *(const float4*)(eb + r0 * 128 + aoff[sub]);
            const float4 v1 = *(const float4*)(eb + (r0 + 8) * 128 + aoff[sub]);
            uint32_t a[4];
            a[0] = pack_relu_h2(v0.x + pv.x, v0.y + pv.y);
            a[1] = pack_relu_h2(v1.x + pv.x, v1.y + pv.y);
            a[2] = pack_relu_h2(v0.z + pv.z, v0.w + pv.w);
            a[3] = pack_relu_h2(v1.z + pv.z, v1.w + pv.w);
#pragma unroll
            for (int ni = 0; ni < 16; ++ni) {
                const uint2 bv =
                    *(const uint2*)(bb + (ni * 8 + g) * 64 + boff[sub]);
                uint32_t b2[2] = {bv.x, bv.y};
                mma16(acc[ni], a, b2);
            }
        }
    }

    const int er0 = e0 + e_g * 16 + g;
    const size_t prow = (size_t)(p0 + p_i) * E_;
    float* o0 = out + (prow + er0) * OUT_;
    float* o1 = out + (prow + er0 + 8) * OUT_;
#pragma unroll
    for (int ni = 0; ni < 16; ++ni) {
        const int ncl = ni * 8 + 2 * t;
        const int n = n0 + ncl;
        if (n < OUT_) {
            const float bz0 = bias_s[ncl], bz1 = bias_s[ncl + 1];
            float2 w0, w1;
            w0.x = fmaxf(acc[ni][0] + bz0, 0.0f);
            w0.y = fmaxf(acc[ni][1] + bz1, 0.0f);
            w1.x = fmaxf(acc[ni][2] + bz0, 0.0f);
            w1.y = fmaxf(acc[ni][3] + bz1, 0.0f);
            *(float2*)(o0 + n) = w0;
            *(float2*)(o1 + n) = w1;
        }
    }
#undef ISSUE
}

// ---------------- launch ----------------
extern "C" void kernel_launch(void* const* d_in, const int* in_sizes, int n_in,
                              void* d_out, int out_size) {
    const float* post  = (const float*)d_in[0];
    const float* emoji = (const float*)d_in[1];
    const float* k1_w  = (const float*)d_in[2];
    const float* k1_b  = (const float*)d_in[3];
    const float* k2_w  = (const float*)d_in[4];
    const float* k2_b  = (const float*)d_in[5];
    const float* l1_w  = (const float*)d_in[6];
    const float* l1_b  = (const float*)d_in[7];
    const float* l2_w  = (const float*)d_in[8];
    const float* l2_b  = (const float*)d_in[9];
    float* out = (float*)d_out;

    __half *pPH, *pEH, *pK1, *pK2, *pL1P, *pL1E, *pPh, *pEh, *pWT;
    float *pPP, *pEE;
    cudaGetSymbolAddress((void**)&pPH, g_posth);
    cudaGetSymbolAddress((void**)&pEH, g_emojih);
    cudaGetSymbolAddress((void**)&pK1, g_k1wh);
    cudaGetSymbolAddress((void**)&pK2, g_k2wh);
    cudaGetSymbolAddress((void**)&pL1P, g_l1ph);
    cudaGetSymbolAddress((void**)&pL1E, g_l1eh);
    cudaGetSymbolAddress((void**)&pPh, g_ph);
    cudaGetSymbolAddress((void**)&pEh, g_eh);
    cudaGetSymbolAddress((void**)&pPP, g_pp);
    cudaGetSymbolAddress((void**)&pEE, g_ee);
    cudaGetSymbolAddress((void**)&pWT, g_wth);

    cudaFuncSetAttribute(big_kernel, cudaFuncAttributeMaxDynamicSharedMemorySize,
                         DYN_SMEM);

    prep<<<960, 256>>>(post, emoji, k1_w, k2_w, l1_w, l2_w,
                       pPH, pEH, pK1, pK2, pL1P, pL1E, pWT);
    // stage 1: p = post@k1 + k1_b ; e = emoji@k2 + k2_b  (fp16 permuted out)
    gemm_h<true><<<dim3(8, 20), 256>>>(pPH, pK1, k1_b, pPh,
                                       pEH, pK2, k2_b, pEh);
    // stage 2: pp = p@l1[:D] ; ee = e@l1[D:] + l1_b  (fp32 permuted out)
    gemm_h<false><<<dim3(8, 20), 256>>>(pPh, pL1P, nullptr, pPP,
                                        pEh, pL1E, l1_b, pEE);
    big_kernel<<<4096, 512, DYN_SMEM>>>(pPP, pEE, pWT, l2_b, out);
}

// round 7
// speedup vs baseline: 2.7328x; 1.0562x over previous
#include <cuda_runtime.h>
#include <cuda_fp16.h>
#include <cstdint>

#define D_ 512
#define P_ 1024
#define E_ 256
#define OUT_ 500

// ---------------- device scratch ----------------
__device__ __half g_posth[P_ * D_];
__device__ __half g_emojih[E_ * D_];
__device__ __half g_k1wh[512 * 512];
__device__ __half g_k2wh[512 * 512];
__device__ __half g_l1ph[512 * 512];
__device__ __half g_l1eh[512 * 512];
__device__ __half g_ph[P_ * 512];
__device__ __half g_eh[E_ * 512];
__device__ float g_pp[P_ * D_];        // fp32, k-permuted
__device__ float g_ee[E_ * D_];        // fp32, k-permuted (+l1_b)
// l2_w in frag-major tiled layout: [nt(4)][chunk(16)][8192B]
// chunk bytes: ((sub*4+t)*8+g)*128 + (ni*8 ^ ((t*2+(g&1))*16)), frag=8B
__device__ __half g_wth[512 * 512];

// ---------------- helpers ----------------
__device__ __forceinline__ uint32_t smem_u32(const void* p) {
    uint32_t a;
    asm("{ .reg .u64 t; cvta.to.shared.u64 t, %1; cvt.u32.u64 %0, t; }" : "=r"(a) : "l"(p));
    return a;
}
__device__ __forceinline__ void mma16(float* d, const uint32_t* a, uint32_t b0, uint32_t b1) {
    asm volatile(
        "mma.sync.aligned.m16n8k16.row.col.f32.f16.f16.f32 "
        "{%0,%1,%2,%3}, {%4,%5,%6,%7}, {%8,%9}, {%0,%1,%2,%3};"
        : "+f"(d[0]), "+f"(d[1]), "+f"(d[2]), "+f"(d[3])
        : "r"(a[0]), "r"(a[1]), "r"(a[2]), "r"(a[3]), "r"(b0), "r"(b1));
}
__device__ __forceinline__ uint32_t pack_relu_h2(float lo, float hi) {
    __half2 h = __floats2half2_rn(fmaxf(lo, 0.0f), fmaxf(hi, 0.0f));
    return *(uint32_t*)&h;
}
__device__ __forceinline__ uint32_t pack_h2(float lo, float hi) {
    __half2 h = __floats2half2_rn(lo, hi);
    return *(uint32_t*)&h;
}
__device__ __forceinline__ void cp16(uint32_t s, const void* g) {
    asm volatile("cp.async.cg.shared.global [%0], [%1], 16;" :: "r"(s), "l"(g));
}
#define CP_COMMIT() asm volatile("cp.async.commit_group;" ::: "memory")
#define CP_WAIT1()  asm volatile("cp.async.wait_group 1;" ::: "memory")

__device__ __forceinline__ int kperm_src(int kp) {
    int j = kp & 15, t = j >> 2, r = j & 3;
    return (kp & ~15) + 2 * t + ((r >> 1) << 3) + (r & 1);
}

// ---------------- prep ----------------
// dest-linear segments: post_h 524288 | emoji_h 131072 | k1wh 262144 |
// k2wh 262144 | l1ph 262144 | l1eh 262144 | wth 262144 = 1966080 = 960*2048
__global__ __launch_bounds__(256) void prep(const float* __restrict__ post,
                                            const float* __restrict__ emoji,
                                            const float* __restrict__ k1w,
                                            const float* __restrict__ k2w,
                                            const float* __restrict__ l1w,
                                            const float* __restrict__ l2w,
                                            __half* __restrict__ post_h,
                                            __half* __restrict__ emoji_h,
                                            __half* __restrict__ k1wh,
                                            __half* __restrict__ k2wh,
                                            __half* __restrict__ l1ph,
                                            __half* __restrict__ l1eh,
                                            __half* __restrict__ wth) {
#pragma unroll
    for (int it = 0; it < 8; it++) {
        int gidx = blockIdx.x * 2048 + it * 256 + threadIdx.x;
        int u = gidx;
        if (u < 524288) {
            int m = u >> 9, ks = kperm_src(u & 511);
            post_h[u] = __float2half_rn(post[m * 512 + ks]);
            continue;
        }
        u -= 524288;
        if (u < 131072) {
            int m = u >> 9, ks = kperm_src(u & 511);
            emoji_h[u] = __float2half_rn(emoji[m * 512 + ks]);
            continue;
        }
        u -= 131072;
        if (u < 262144) {
            int n = u >> 9, ks = kperm_src(u & 511);
            k1wh[u] = __float2half_rn(k1w[ks * 512 + n]);
            continue;
        }
        u -= 262144;
        if (u < 262144) {
            int n = u >> 9, ks = kperm_src(u & 511);
            k2wh[u] = __float2half_rn(k2w[ks * 512 + n]);
            continue;
        }
        u -= 262144;
        if (u < 262144) {
            int n = u >> 9, ks = kperm_src(u & 511);
            l1ph[u] = __float2half_rn(l1w[ks * 512 + n]);
            continue;
        }
        u -= 262144;
        if (u < 262144) {
            int n = u >> 9, ks = kperm_src(u & 511);
            l1eh[u] = __float2half_rn(l1w[(512 + ks) * 512 + n]);
            continue;
        }
        u -= 262144;
        {
            // frag-major tiled layout for big_kernel B
            int nt = u >> 16;
            int rem = u & 65535;
            int c = rem >> 12;
            int qb = (rem & 4095) * 2;
            int s3 = qb >> 7;
            int sub = s3 >> 5, tt = (s3 >> 3) & 3, gg = s3 & 7;
            int Y = (qb & 127) ^ ((tt * 2 + (gg & 1)) * 16);
            int ni = Y >> 3;
            int j = (Y >> 1) & 3;
            int k = c * 32 + sub * 16 + 2 * (tt + ((j >> 1) << 2)) + (j & 1);
            int n = nt * 128 + ni * 8 + gg;
            float v = (n < OUT_) ? l2w[k * OUT_ + n] : 0.0f;
            wth[u] = __float2half_rn(v);
        }
    }
}

// ---------------- fp16 MMA GEMM for the small chain (unchanged from R6) ----
#define GH_BUF 12288

template <bool OUT16>
__global__ __launch_bounds__(256) void gemm_h(const __half* __restrict__ A0,
                                              const __half* __restrict__ B0,
                                              const float* __restrict__ bias0,
                                              void* __restrict__ out0,
                                              const __half* __restrict__ A1,
                                              const __half* __restrict__ B1,
                                              const float* __restrict__ bias1,
                                              void* __restrict__ out1) {
    __shared__ __align__(16) char sm[3 * GH_BUF];
    const uint32_t sbu = smem_u32(sm);

    const int tid = threadIdx.x;
    const __half* A;
    const __half* B;
    const float* bias;
    void* out;
    int mrow0;
    if (blockIdx.y < 16) {
        A = A0; B = B0; bias = bias0; out = out0; mrow0 = blockIdx.y * 64;
    } else {
        A = A1; B = B1; bias = bias1; out = out1; mrow0 = (blockIdx.y - 16) * 64;
    }
    const int ncol0 = blockIdx.x * 64;

    const int wid = tid >> 5, lane = tid & 31;
    const int g = lane >> 2, t = lane & 3;
    const int mgrp = wid >> 1, nw = (wid & 1) * 32;

    const int srow = tid >> 2, seg = tid & 3;
    const char* a_src = (const char*)(A + (size_t)(mrow0 + srow) * 512);
    const char* b_src = (const char*)(B + (size_t)(ncol0 + srow) * 512);
    const uint32_t a_d = srow * 96u + seg * 16u;
    const uint32_t b_d = 6144u + srow * 96u + seg * 16u;

#define GH_ISSUE(c)                                             \
    do {                                                        \
        uint32_t _b = sbu + ((c) % 3) * GH_BUF;                 \
        cp16(_b + a_d, a_src + (c) * 64 + seg * 16);            \
        cp16(_b + b_d, b_src + (c) * 64 + seg * 16);            \
    } while (0)

    GH_ISSUE(0); CP_COMMIT();
    GH_ISSUE(1); CP_COMMIT();

    float acc[4][4];
#pragma unroll
    for (int ni = 0; ni < 4; ni++)
#pragma unroll
        for (int j = 0; j < 4; j++) acc[ni][j] = 0.0f;

    const int arow = mgrp * 16 + g;

#pragma unroll 1
    for (int c = 0; c < 16; ++c) {
        CP_WAIT1();
        __syncthreads();
        if (c + 2 < 16) { GH_ISSUE(c + 2); CP_COMMIT(); }
        else { CP_COMMIT(); }

        const char* ab = sm + (c % 3) * GH_BUF;
        const char* bb = ab + 6144;
#pragma unroll
        for (int sub = 0; sub < 2; ++sub) {
            const uint32_t ko = sub * 32 + t * 8;
            const uint2 alo = *(const uint2*)(ab + arow * 96 + ko);
            const uint2 ahi = *(const uint2*)(ab + (arow + 8) * 96 + ko);
            uint32_t a[4] = {alo.x, ahi.x, alo.y, ahi.y};
#pragma unroll
            for (int ni = 0; ni < 4; ++ni) {
                const uint2 bv = *(const uint2*)(bb + (nw + ni * 8 + g) * 96 + ko);
                mma16(acc[ni], a, bv.x, bv.y);
            }
        }
    }

    const int m0 = mrow0 + mgrp * 16 + g;
#pragma unroll
    for (int ni = 0; ni < 4; ++ni) {
        const int ncol = ncol0 + nw + ni * 8;
        const int off = (ncol >> 4) * 16 + 4 * t + 2 * (ni & 1);
        const float b0v = bias ? bias[ncol + 2 * t] : 0.0f;
        const float b1v = bias ? bias[ncol + 2 * t + 1] : 0.0f;
        if (OUT16) {
            __half* o = (__half*)out;
            *(uint32_t*)(o + (size_t)m0 * 512 + off) =
                pack_h2(acc[ni][0] + b0v, acc[ni][1] + b1v);
            *(uint32_t*)(o + (size_t)(m0 + 8) * 512 + off) =
                pack_h2(acc[ni][2] + b0v, acc[ni][3] + b1v);
        } else {
            float* o = (float*)out;
            float2 w0 = {acc[ni][0] + b0v, acc[ni][1] + b1v};
            float2 w1 = {acc[ni][2] + b0v, acc[ni][3] + b1v};
            *(float2*)(o + (size_t)m0 * 512 + off) = w0;
            *(float2*)(o + (size_t)(m0 + 8) * 512 + off) = w1;
        }
    }
#undef GH_ISSUE
}

// ---------------- main kernel ----------------
#define EE_B 16384u
#define B_B  8192u
#define OFF_B  (3 * EE_B)
#define OFF_PP (OFF_B + 3 * B_B)
#define OFF_BI (OFF_PP + 4096u)
#define DYN_SMEM (OFF_BI + 512u)

__global__ __launch_bounds__(512, 1) void big_kernel(const float* __restrict__ pp,
                                                     const float* __restrict__ ee,
                                                     const __half* __restrict__ wth,
                                                     const float* __restrict__ bias,
                                                     float* __restrict__ out) {
    extern __shared__ char dsm[];
    const uint32_t sbu = smem_u32(dsm);

    const int tid = threadIdx.x;
    const int bid = blockIdx.x;
    const int nt = bid & 3, eh = (bid >> 2) & 1, pg = bid >> 3;
    const int n0 = nt * 128, e0 = eh * 128, p0 = pg * 2;

    const int wid = tid >> 5, lane = tid & 31;
    const int g = lane >> 2, t = lane & 3;
    const int p_i = wid >> 3;
    const int e_g = wid & 7;

    // ---- staging ----
    const int srow = tid >> 2;
    const int es2 = (tid & 3) * 2;
    const char* ee_src = (const char*)(ee + (size_t)(e0 + srow) * 512);
    const char* wt_src = (const char*)(wth + (size_t)nt * 65536);
    const uint32_t eswz_w = (uint32_t)((srow & 1) * 64);
    const uint32_t ee_d0 = srow * 128u + (((uint32_t)es2 * 16u) ^ eswz_w);
    const uint32_t ee_d1 = srow * 128u + (((uint32_t)(es2 + 1) * 16u) ^ eswz_w);
    const uint32_t b_d = (uint32_t)tid * 16u;

#define ISSUE(c)                                                        \
    do {                                                                \
        uint32_t _eb = sbu + ((c) % 3) * EE_B;                          \
        uint32_t _bb = sbu + OFF_B + ((c) % 3) * B_B;                   \
        const char* _es = ee_src + (c) * 128;                           \
        cp16(_eb + ee_d0, _es + es2 * 16);                              \
        cp16(_eb + ee_d1, _es + es2 * 16 + 16);                         \
        cp16(_bb + b_d, wt_src + (c) * 8192 + tid * 16);                \
    } while (0)

    ISSUE(0); CP_COMMIT();
    ISSUE(1); CP_COMMIT();

    float* pp_s = (float*)(dsm + OFF_PP);
    float* bias_s = (float*)(dsm + OFF_BI);
    for (int i = tid; i < 1024; i += 512)
        pp_s[i] = pp[(size_t)(p0 + (i >> 9)) * 512 + (i & 511)];
    if (tid < 128) bias_s[tid] = (n0 + tid < OUT_) ? bias[n0 + tid] : 0.0f;

    float acc[16][4];
#pragma unroll
    for (int ni = 0; ni < 16; ni++)
#pragma unroll
        for (int j = 0; j < 4; j++) acc[ni][j] = 0.0f;

    // read-side constants
    const int r0 = e_g * 16 + g;
    const uint32_t eswz_r = (uint32_t)((g & 1) * 64);
    const uint32_t aoff[2] = {
        (((uint32_t)(0 * 64 + t * 16)) ^ eswz_r),
        (((uint32_t)(1 * 64 + t * 16)) ^ eswz_r)};
    const uint32_t brow = (uint32_t)(t * 1024 + g * 128);  // + sub*4096
    const uint32_t bxor = (uint32_t)((t * 2 + (g & 1)) * 16);

#pragma unroll 1
    for (int c = 0; c < 16; ++c) {
        CP_WAIT1();
        __syncthreads();
        if (c + 2 < 16) { ISSUE(c + 2); CP_COMMIT(); }
        else { CP_COMMIT(); }

        const char* eb = dsm + (c % 3) * EE_B;
        const char* bb = dsm + OFF_B + (c % 3) * B_B + brow;
        const float* ppc = pp_s + p_i * 512 + c * 32;

#pragma unroll
        for (int sub = 0; sub < 2; ++sub) {
            const float4 pv = *(const float4*)(ppc + sub * 16 + t * 4);
            const float4 v0 = *(const float4*)(eb + r0 * 128 + aoff[sub]);
            const float4 v1 = *(const float4*)(eb + (r0 + 8) * 128 + aoff[sub]);
            uint32_t a[4];
            a[0] = pack_relu_h2(v0.x + pv.x, v0.y + pv.y);
            a[1] = pack_relu_h2(v1.x + pv.x, v1.y + pv.y);
            a[2] = pack_relu_h2(v0.z + pv.z, v0.w + pv.w);
            a[3] = pack_relu_h2(v1.z + pv.z, v1.w + pv.w);

            const char* bs = bb + sub * 4096;
            uint4 bq = *(const uint4*)(bs + (0u ^ bxor));
#pragma unroll
            for (int nip = 0; nip < 8; ++nip) {
                uint4 bq_n;
                if (nip < 7)
                    bq_n = *(const uint4*)(bs + (((uint32_t)(nip + 1) * 16u) ^ bxor));
                mma16(acc[2 * nip], a, bq.x, bq.y);
                mma16(acc[2 * nip + 1], a, bq.z, bq.w);
                if (nip < 7) bq = bq_n;
            }
        }
    }

    // ---- epilogue ----
    const int er0 = e0 + e_g * 16 + g;
    const size_t prow = (size_t)(p0 + p_i) * E_;
    float* o0 = out + (prow + er0) * OUT_;
    float* o1 = out + (prow + er0 + 8) * OUT_;
#pragma unroll
    for (int ni = 0; ni < 16; ++ni) {
        const int ncl = ni * 8 + 2 * t;
        const int n = n0 + ncl;
        if (n < OUT_) {
            const float bz0 = bias_s[ncl], bz1 = bias_s[ncl + 1];
            float2 w0, w1;
            w0.x = fmaxf(acc[ni][0] + bz0, 0.0f);
            w0.y = fmaxf(acc[ni][1] + bz1, 0.0f);
            w1.x = fmaxf(acc[ni][2] + bz0, 0.0f);
            w1.y = fmaxf(acc[ni][3] + bz1, 0.0f);
            *(float2*)(o0 + n) = w0;
            *(float2*)(o1 + n) = w1;
        }
    }
#undef ISSUE
}

// ---------------- launch ----------------
extern "C" void kernel_launch(void* const* d_in, const int* in_sizes, int n_in,
                              void* d_out, int out_size) {
    const float* post  = (const float*)d_in[0];
    const float* emoji = (const float*)d_in[1];
    const float* k1_w  = (const float*)d_in[2];
    const float* k1_b  = (const float*)d_in[3];
    const float* k2_w  = (const float*)d_in[4];
    const float* k2_b  = (const float*)d_in[5];
    const float* l1_w  = (const float*)d_in[6];
    const float* l1_b  = (const float*)d_in[7];
    const float* l2_w  = (const float*)d_in[8];
    const float* l2_b  = (const float*)d_in[9];
    float* out = (float*)d_out;

    __half *pPH, *pEH, *pK1, *pK2, *pL1P, *pL1E, *pPh, *pEh, *pWT;
    float *pPP, *pEE;
    cudaGetSymbolAddress((void**)&pPH, g_posth);
    cudaGetSymbolAddress((void**)&pEH, g_emojih);
    cudaGetSymbolAddress((void**)&pK1, g_k1wh);
    cudaGetSymbolAddress((void**)&pK2, g_k2wh);
    cudaGetSymbolAddress((void**)&pL1P, g_l1ph);
    cudaGetSymbolAddress((void**)&pL1E, g_l1eh);
    cudaGetSymbolAddress((void**)&pPh, g_ph);
    cudaGetSymbolAddress((void**)&pEh, g_eh);
    cudaGetSymbolAddress((void**)&pPP, g_pp);
    cudaGetSymbolAddress((void**)&pEE, g_ee);
    cudaGetSymbolAddress((void**)&pWT, g_wth);

    cudaFuncSetAttribute(big_kernel, cudaFuncAttributeMaxDynamicSharedMemorySize,
                         DYN_SMEM);

    prep<<<960, 256>>>(post, emoji, k1_w, k2_w, l1_w, l2_w,
                       pPH, pEH, pK1, pK2, pL1P, pL1E, pWT);
    gemm_h<true><<<dim3(8, 20), 256>>>(pPH, pK1, k1_b, pPh,
                                       pEH, pK2, k2_b, pEh);
    gemm_h<false><<<dim3(8, 20), 256>>>(pPh, pL1P, nullptr, pPP,
                                        pEh, pL1E, l1_b, pEE);
    big_kernel<<<4096, 512, DYN_SMEM>>>(pPP, pEE, pWT, l2_b, out);
}

// round 8
// speedup vs baseline: 2.7414x; 1.0031x over previous
#include <cuda_runtime.h>
#include <cuda_fp16.h>
#include <cstdint>

#define D_ 512
#define P_ 1024
#define E_ 256
#define OUT_ 500

// ---------------- device scratch ----------------
__device__ __half g_posth[P_ * D_];
__device__ __half g_emojih[E_ * D_];
__device__ __half g_k1wh[512 * 512];
__device__ __half g_k2wh[512 * 512];
__device__ __half g_l1ph[512 * 512];
__device__ __half g_l1eh[512 * 512];
__device__ __half g_ph[P_ * 512];
__device__ __half g_eh[E_ * 512];
__device__ float g_pp[P_ * D_];        // fp32, k-permuted
__device__ float g_ee[E_ * D_];        // fp32, k-permuted (+l1_b)
// l2_w frag-major tiled for 64-n tiles: [nt(8)][chunk(16)][4096B]
// chunk byte: sub*2048 + t*512 + g*64 + ((ni*8) ^ (t*16)), frag = 8B
__device__ __half g_wth[512 * 512];

// ---------------- helpers ----------------
__device__ __forceinline__ uint32_t smem_u32(const void* p) {
    uint32_t a;
    asm("{ .reg .u64 t; cvta.to.shared.u64 t, %1; cvt.u32.u64 %0, t; }" : "=r"(a) : "l"(p));
    return a;
}
__device__ __forceinline__ void mma16(float* d, const uint32_t* a, uint32_t b0, uint32_t b1) {
    asm volatile(
        "mma.sync.aligned.m16n8k16.row.col.f32.f16.f16.f32 "
        "{%0,%1,%2,%3}, {%4,%5,%6,%7}, {%8,%9}, {%0,%1,%2,%3};"
        : "+f"(d[0]), "+f"(d[1]), "+f"(d[2]), "+f"(d[3])
        : "r"(a[0]), "r"(a[1]), "r"(a[2]), "r"(a[3]), "r"(b0), "r"(b1));
}
__device__ __forceinline__ uint32_t pack_relu_h2(float lo, float hi) {
    __half2 h = __floats2half2_rn(fmaxf(lo, 0.0f), fmaxf(hi, 0.0f));
    return *(uint32_t*)&h;
}
__device__ __forceinline__ uint32_t pack_h2(float lo, float hi) {
    __half2 h = __floats2half2_rn(lo, hi);
    return *(uint32_t*)&h;
}
__device__ __forceinline__ void cp16(uint32_t s, const void* g) {
    asm volatile("cp.async.cg.shared.global [%0], [%1], 16;" :: "r"(s), "l"(g));
}
#define CP_COMMIT() asm volatile("cp.async.commit_group;" ::: "memory")
#define CP_WAIT1()  asm volatile("cp.async.wait_group 1;" ::: "memory")
#define CP_WAIT2()  asm volatile("cp.async.wait_group 2;" ::: "memory")

__device__ __forceinline__ int kperm_src(int kp) {
    int j = kp & 15, t = j >> 2, r = j & 3;
    return (kp & ~15) + 2 * t + ((r >> 1) << 3) + (r & 1);
}

// ---------------- prep ----------------
__global__ __launch_bounds__(256) void prep(const float* __restrict__ post,
                                            const float* __restrict__ emoji,
                                            const float* __restrict__ k1w,
                                            const float* __restrict__ k2w,
                                            const float* __restrict__ l1w,
                                            const float* __restrict__ l2w,
                                            __half* __restrict__ post_h,
                                            __half* __restrict__ emoji_h,
                                            __half* __restrict__ k1wh,
                                            __half* __restrict__ k2wh,
                                            __half* __restrict__ l1ph,
                                            __half* __restrict__ l1eh,
                                            __half* __restrict__ wth) {
#pragma unroll
    for (int it = 0; it < 8; it++) {
        int gidx = blockIdx.x * 2048 + it * 256 + threadIdx.x;
        int u = gidx;
        if (u < 524288) {
            int m = u >> 9, ks = kperm_src(u & 511);
            post_h[u] = __float2half_rn(post[m * 512 + ks]);
            continue;
        }
        u -= 524288;
        if (u < 131072) {
            int m = u >> 9, ks = kperm_src(u & 511);
            emoji_h[u] = __float2half_rn(emoji[m * 512 + ks]);
            continue;
        }
        u -= 131072;
        if (u < 262144) {
            int n = u >> 9, ks = kperm_src(u & 511);
            k1wh[u] = __float2half_rn(k1w[ks * 512 + n]);
            continue;
        }
        u -= 262144;
        if (u < 262144) {
            int n = u >> 9, ks = kperm_src(u & 511);
            k2wh[u] = __float2half_rn(k2w[ks * 512 + n]);
            continue;
        }
        u -= 262144;
        if (u < 262144) {
            int n = u >> 9, ks = kperm_src(u & 511);
            l1ph[u] = __float2half_rn(l1w[ks * 512 + n]);
            continue;
        }
        u -= 262144;
        if (u < 262144) {
            int n = u >> 9, ks = kperm_src(u & 511);
            l1eh[u] = __float2half_rn(l1w[(512 + ks) * 512 + n]);
            continue;
        }
        u -= 262144;
        {
            // frag-major layout for 64-n tiles
            int nt = u >> 15;
            int rem = u & 32767;
            int c = rem >> 11;
            int byte = (rem & 2047) * 2;
            int sub = byte >> 11;
            int tt = (byte >> 9) & 3;
            int gg = (byte >> 6) & 7;
            int y = (byte & 63) ^ (tt * 16);
            int ni = y >> 3;
            int h = (y >> 1) & 3;
            int k = c * 32 + sub * 16 + 2 * tt + ((h >> 1) << 3) + (h & 1);
            int n = nt * 64 + ni * 8 + gg;
            float v = (n < OUT_) ? l2w[k * OUT_ + n] : 0.0f;
            wth[u] = __float2half_rn(v);
        }
    }
}

// ---------------- fp16 MMA GEMM for the small chain (unchanged) ----------------
#define GH_BUF 12288

template <bool OUT16>
__global__ __launch_bounds__(256) void gemm_h(const __half* __restrict__ A0,
                                              const __half* __restrict__ B0,
                                              const float* __restrict__ bias0,
                                              void* __restrict__ out0,
                                              const __half* __restrict__ A1,
                                              const __half* __restrict__ B1,
                                              const float* __restrict__ bias1,
                                              void* __restrict__ out1) {
    __shared__ __align__(16) char sm[3 * GH_BUF];
    const uint32_t sbu = smem_u32(sm);

    const int tid = threadIdx.x;
    const __half* A;
    const __half* B;
    const float* bias;
    void* out;
    int mrow0;
    if (blockIdx.y < 16) {
        A = A0; B = B0; bias = bias0; out = out0; mrow0 = blockIdx.y * 64;
    } else {
        A = A1; B = B1; bias = bias1; out = out1; mrow0 = (blockIdx.y - 16) * 64;
    }
    const int ncol0 = blockIdx.x * 64;

    const int wid = tid >> 5, lane = tid & 31;
    const int g = lane >> 2, t = lane & 3;
    const int mgrp = wid >> 1, nw = (wid & 1) * 32;

    const int srow = tid >> 2, seg = tid & 3;
    const char* a_src = (const char*)(A + (size_t)(mrow0 + srow) * 512);
    const char* b_src = (const char*)(B + (size_t)(ncol0 + srow) * 512);
    const uint32_t a_d = srow * 96u + seg * 16u;
    const uint32_t b_d = 6144u + srow * 96u + seg * 16u;

#define GH_ISSUE(c)                                             \
    do {                                                        \
        uint32_t _b = sbu + ((c) % 3) * GH_BUF;                 \
        cp16(_b + a_d, a_src + (c) * 64 + seg * 16);            \
        cp16(_b + b_d, b_src + (c) * 64 + seg * 16);            \
    } while (0)

    GH_ISSUE(0); CP_COMMIT();
    GH_ISSUE(1); CP_COMMIT();

    float acc[4][4];
#pragma unroll
    for (int ni = 0; ni < 4; ni++)
#pragma unroll
        for (int j = 0; j < 4; j++) acc[ni][j] = 0.0f;

    const int arow = mgrp * 16 + g;

#pragma unroll 1
    for (int c = 0; c < 16; ++c) {
        CP_WAIT1();
        __syncthreads();
        if (c + 2 < 16) { GH_ISSUE(c + 2); CP_COMMIT(); }
        else { CP_COMMIT(); }

        const char* ab = sm + (c % 3) * GH_BUF;
        const char* bb = ab + 6144;
#pragma unroll
        for (int sub = 0; sub < 2; ++sub) {
            const uint32_t ko = sub * 32 + t * 8;
            const uint2 alo = *(const uint2*)(ab + arow * 96 + ko);
            const uint2 ahi = *(const uint2*)(ab + (arow + 8) * 96 + ko);
            uint32_t a[4] = {alo.x, ahi.x, alo.y, ahi.y};
#pragma unroll
            for (int ni = 0; ni < 4; ++ni) {
                const uint2 bv = *(const uint2*)(bb + (nw + ni * 8 + g) * 96 + ko);
                mma16(acc[ni], a, bv.x, bv.y);
            }
        }
    }

    const int m0 = mrow0 + mgrp * 16 + g;
#pragma unroll
    for (int ni = 0; ni < 4; ++ni) {
        const int ncol = ncol0 + nw + ni * 8;
        const int off = (ncol >> 4) * 16 + 4 * t + 2 * (ni & 1);
        const float b0v = bias ? bias[ncol + 2 * t] : 0.0f;
        const float b1v = bias ? bias[ncol + 2 * t + 1] : 0.0f;
        if (OUT16) {
            __half* o = (__half*)out;
            *(uint32_t*)(o + (size_t)m0 * 512 + off) =
                pack_h2(acc[ni][0] + b0v, acc[ni][1] + b1v);
            *(uint32_t*)(o + (size_t)(m0 + 8) * 512 + off) =
                pack_h2(acc[ni][2] + b0v, acc[ni][3] + b1v);
        } else {
            float* o = (float*)out;
            float2 w0 = {acc[ni][0] + b0v, acc[ni][1] + b1v};
            float2 w1 = {acc[ni][2] + b0v, acc[ni][3] + b1v};
            *(float2*)(o + (size_t)m0 * 512 + off) = w0;
            *(float2*)(o + (size_t)(m0 + 8) * 512 + off) = w1;
        }
    }
#undef GH_ISSUE
}

// ---------------- main kernel ----------------
// CTA = (2p, 64e, 64n), 256 thr = 8 warps = 2p x 4 e-groups, warp 16e x 64n.
// 4-stage cp.async, 3 CTAs/SM. grid 16384: bid = pg*32 + eq*8 + nt
#define EE_BUF 8192u
#define B_BUF  4096u
#define OFF_B  (4 * EE_BUF)           // 32768
#define OFF_PP (OFF_B + 4 * B_BUF)    // 49152
#define OFF_BI (OFF_PP + 4096u)       // 53248
#define DYN_SMEM (OFF_BI + 256u)      // 53504

__global__ __launch_bounds__(256, 3) void big_kernel(const float* __restrict__ pp,
                                                     const float* __restrict__ ee,
                                                     const __half* __restrict__ wth,
                                                     const float* __restrict__ bias,
                                                     float* __restrict__ out) {
    extern __shared__ char dsm[];
    const uint32_t sbu = smem_u32(dsm);

    const int tid = threadIdx.x;
    const int bid = blockIdx.x;
    const int nt = bid & 7, eq = (bid >> 3) & 3, pg = bid >> 5;
    const int n0 = nt * 64, e0 = eq * 64, p0 = pg * 2;

    const int wid = tid >> 5, lane = tid & 31;
    const int g = lane >> 2, t = lane & 3;
    const int p_i = wid >> 2;       // 0..1
    const int e_g = wid & 3;        // 0..3

    // ---- staging ----
    const int srow = tid >> 2;                   // 0..63
    const int es2 = (tid & 3) * 2;
    const char* ee_src = (const char*)(ee + (size_t)(e0 + srow) * 512);
    const char* wt_src = (const char*)(wth + (size_t)nt * 32768);
    const uint32_t eswz_w = (uint32_t)((srow & 1) * 64);
    const uint32_t ee_d0 = srow * 128u + (((uint32_t)es2 * 16u) ^ eswz_w);
    const uint32_t ee_d1 = srow * 128u + (((uint32_t)(es2 + 1) * 16u) ^ eswz_w);
    const uint32_t b_d = OFF_B + (uint32_t)tid * 16u;

#define ISSUE(c)                                                        \
    do {                                                                \
        uint32_t _st = ((c) & 3);                                       \
        const char* _es = ee_src + (c) * 128;                           \
        cp16(sbu + _st * EE_BUF + ee_d0, _es + es2 * 16);               \
        cp16(sbu + _st * EE_BUF + ee_d1, _es + es2 * 16 + 16);          \
        cp16(sbu + _st * B_BUF + b_d, wt_src + (c) * 4096 + tid * 16);  \
    } while (0)

    ISSUE(0); CP_COMMIT();
    ISSUE(1); CP_COMMIT();
    ISSUE(2); CP_COMMIT();

    float* pp_s = (float*)(dsm + OFF_PP);
    float* bias_s = (float*)(dsm + OFF_BI);
    for (int i = tid; i < 1024; i += 256)
        pp_s[i] = pp[(size_t)(p0 + (i >> 9)) * 512 + (i & 511)];
    if (tid < 64) bias_s[tid] = (n0 + tid < OUT_) ? bias[n0 + tid] : 0.0f;

    float acc[8][4];
#pragma unroll
    for (int ni = 0; ni < 8; ni++)
#pragma unroll
        for (int j = 0; j < 4; j++) acc[ni][j] = 0.0f;

    // read-side constants
    const int r0 = e_g * 16 + g;
    const uint32_t eswz_r = (uint32_t)((g & 1) * 64);
    const uint32_t aoff[2] = {
        (((uint32_t)(0 * 64 + t * 16)) ^ eswz_r),
        (((uint32_t)(1 * 64 + t * 16)) ^ eswz_r)};
    const uint32_t broff = (uint32_t)(t * 512 + g * 64);
    const uint32_t bxor = (uint32_t)(t * 16);

#pragma unroll 1
    for (int c = 0; c < 16; ++c) {
        CP_WAIT2();
        __syncthreads();
        if (c + 3 < 16) { ISSUE(c + 3); CP_COMMIT(); }
        else { CP_COMMIT(); }

        const char* eb = dsm + (c & 3) * EE_BUF;
        const char* bb = dsm + OFF_B + (c & 3) * B_BUF + broff;
        const float* ppc = pp_s + p_i * 512 + c * 32;

#pragma unroll
        for (int sub = 0; sub < 2; ++sub) {
            const float4 pv = *(const float4*)(ppc + sub * 16 + t * 4);
            const float4 v0 = *(const float4*)(eb + r0 * 128 + aoff[sub]);
            const float4 v1 = *(const float4*)(eb + (r0 + 8) * 128 + aoff[sub]);
            uint32_t a[4];
            a[0] = pack_relu_h2(v0.x + pv.x, v0.y + pv.y);
            a[1] = pack_relu_h2(v1.x + pv.x, v1.y + pv.y);
            a[2] = pack_relu_h2(v0.z + pv.z, v0.w + pv.w);
            a[3] = pack_relu_h2(v1.z + pv.z, v1.w + pv.w);

            const char* bs = bb + sub * 2048;
            uint4 bq = *(const uint4*)(bs + (0u ^ bxor));
#pragma unroll
            for (int nip = 0; nip < 4; ++nip) {
                uint4 bq_n;
                if (nip < 3)
                    bq_n = *(const uint4*)(bs + (((uint32_t)(nip + 1) * 16u) ^ bxor));
                mma16(acc[2 * nip], a, bq.x, bq.y);
                mma16(acc[2 * nip + 1], a, bq.z, bq.w);
                if (nip < 3) bq = bq_n;
            }
        }
    }

    // ---- epilogue ----
    const int er0 = e0 + e_g * 16 + g;
    const size_t prow = (size_t)(p0 + p_i) * E_;
    float* o0 = out + (prow + er0) * OUT_;
    float* o1 = out + (prow + er0 + 8) * OUT_;
#pragma unroll
    for (int ni = 0; ni < 8; ++ni) {
        const int ncl = ni * 8 + 2 * t;
        const int n = n0 + ncl;
        if (n < OUT_) {
            const float bz0 = bias_s[ncl], bz1 = bias_s[ncl + 1];
            float2 w0, w1;
            w0.x = fmaxf(acc[ni][0] + bz0, 0.0f);
            w0.y = fmaxf(acc[ni][1] + bz1, 0.0f);
            w1.x = fmaxf(acc[ni][2] + bz0, 0.0f);
            w1.y = fmaxf(acc[ni][3] + bz1, 0.0f);
            *(float2*)(o0 + n) = w0;
            *(float2*)(o1 + n) = w1;
        }
    }
#undef ISSUE
}

// ---------------- launch ----------------
extern "C" void kernel_launch(void* const* d_in, const int* in_sizes, int n_in,
                              void* d_out, int out_size) {
    const float* post  = (const float*)d_in[0];
    const float* emoji = (const float*)d_in[1];
    const float* k1_w  = (const float*)d_in[2];
    const float* k1_b  = (const float*)d_in[3];
    const float* k2_w  = (const float*)d_in[4];
    const float* k2_b  = (const float*)d_in[5];
    const float* l1_w  = (const float*)d_in[6];
    const float* l1_b  = (const float*)d_in[7];
    const float* l2_w  = (const float*)d_in[8];
    const float* l2_b  = (const float*)d_in[9];
    float* out = (float*)d_out;

    __half *pPH, *pEH, *pK1, *pK2, *pL1P, *pL1E, *pPh, *pEh, *pWT;
    float *pPP, *pEE;
    cudaGetSymbolAddress((void**)&pPH, g_posth);
    cudaGetSymbolAddress((void**)&pEH, g_emojih);
    cudaGetSymbolAddress((void**)&pK1, g_k1wh);
    cudaGetSymbolAddress((void**)&pK2, g_k2wh);
    cudaGetSymbolAddress((void**)&pL1P, g_l1ph);
    cudaGetSymbolAddress((void**)&pL1E, g_l1eh);
    cudaGetSymbolAddress((void**)&pPh, g_ph);
    cudaGetSymbolAddress((void**)&pEh, g_eh);
    cudaGetSymbolAddress((void**)&pPP, g_pp);
    cudaGetSymbolAddress((void**)&pEE, g_ee);
    cudaGetSymbolAddress((void**)&pWT, g_wth);

    cudaFuncSetAttribute(big_kernel, cudaFuncAttributeMaxDynamicSharedMemorySize,
                         DYN_SMEM);

    prep<<<960, 256>>>(post, emoji, k1_w, k2_w, l1_w, l2_w,
                       pPH, pEH, pK1, pK2, pL1P, pL1E, pWT);
    gemm_h<true><<<dim3(8, 20), 256>>>(pPH, pK1, k1_b, pPh,
                                       pEH, pK2, k2_b, pEh);
    gemm_h<false><<<dim3(8, 20), 256>>>(pPh, pL1P, nullptr, pPP,
                                        pEh, pL1E, l1_b, pEE);
    big_kernel<<<16384, 256, DYN_SMEM>>>(pPP, pEE, pWT, l2_b, out);
}

// round 9
// speedup vs baseline: 3.2707x; 1.1931x over previous
#include <cuda_runtime.h>
#include <cuda_fp16.h>
#include <cstdint>

#define D_ 512
#define P_ 1024
#define E_ 256
#define OUT_ 500

// ---------------- device scratch ----------------
__device__ __half g_posth[P_ * D_];
__device__ __half g_emojih[E_ * D_];
__device__ __half g_k1wh[512 * 512];
__device__ __half g_k2wh[512 * 512];
__device__ __half g_l1ph[512 * 512];
__device__ __half g_l1eh[512 * 512];
__device__ __half g_ph[P_ * 512];
__device__ __half g_eh[E_ * 512];
__device__ float g_pp[P_ * D_];        // fp32, k-permuted
__device__ float g_ee[E_ * D_];        // fp32, k-permuted (+l1_b)
// l2_w frag-major tiled for 64-n tiles: [nt(8)][chunk(16)][4096B]
// chunk byte: sub*2048 + t*512 + g*64 + ((ni*8) ^ (t*16)), frag = 8B
__device__ __half g_wth[512 * 512];

// ---------------- helpers ----------------
__device__ __forceinline__ uint32_t smem_u32(const void* p) {
    uint32_t a;
    asm("{ .reg .u64 t; cvta.to.shared.u64 t, %1; cvt.u32.u64 %0, t; }" : "=r"(a) : "l"(p));
    return a;
}
__device__ __forceinline__ void mma16(float* d, const uint32_t* a, uint32_t b0, uint32_t b1) {
    asm volatile(
        "mma.sync.aligned.m16n8k16.row.col.f32.f16.f16.f32 "
        "{%0,%1,%2,%3}, {%4,%5,%6,%7}, {%8,%9}, {%0,%1,%2,%3};"
        : "+f"(d[0]), "+f"(d[1]), "+f"(d[2]), "+f"(d[3])
        : "r"(a[0]), "r"(a[1]), "r"(a[2]), "r"(a[3]), "r"(b0), "r"(b1));
}
__device__ __forceinline__ uint32_t pack_relu_h2(float lo, float hi) {
    __half2 h = __floats2half2_rn(fmaxf(lo, 0.0f), fmaxf(hi, 0.0f));
    return *(uint32_t*)&h;
}
__device__ __forceinline__ uint32_t pack_h2(float lo, float hi) {
    __half2 h = __floats2half2_rn(lo, hi);
    return *(uint32_t*)&h;
}
__device__ __forceinline__ void cp16(uint32_t s, const void* g) {
    asm volatile("cp.async.cg.shared.global [%0], [%1], 16;" :: "r"(s), "l"(g));
}
#define CP_COMMIT() asm volatile("cp.async.commit_group;" ::: "memory")
#define CP_WAIT1()  asm volatile("cp.async.wait_group 1;" ::: "memory")
#define CP_WAIT2()  asm volatile("cp.async.wait_group 2;" ::: "memory")

__device__ __forceinline__ int kperm_src(int kp) {
    int j = kp & 15, t = j >> 2, r = j & 3;
    return (kp & ~15) + 2 * t + ((r >> 1) << 3) + (r & 1);
}

// ---------------- prep (unchanged) ----------------
__global__ __launch_bounds__(256) void prep(const float* __restrict__ post,
                                            const float* __restrict__ emoji,
                                            const float* __restrict__ k1w,
                                            const float* __restrict__ k2w,
                                            const float* __restrict__ l1w,
                                            const float* __restrict__ l2w,
                                            __half* __restrict__ post_h,
                                            __half* __restrict__ emoji_h,
                                            __half* __restrict__ k1wh,
                                            __half* __restrict__ k2wh,
                                            __half* __restrict__ l1ph,
                                            __half* __restrict__ l1eh,
                                            __half* __restrict__ wth) {
#pragma unroll
    for (int it = 0; it < 8; it++) {
        int gidx = blockIdx.x * 2048 + it * 256 + threadIdx.x;
        int u = gidx;
        if (u < 524288) {
            int m = u >> 9, ks = kperm_src(u & 511);
            post_h[u] = __float2half_rn(post[m * 512 + ks]);
            continue;
        }
        u -= 524288;
        if (u < 131072) {
            int m = u >> 9, ks = kperm_src(u & 511);
            emoji_h[u] = __float2half_rn(emoji[m * 512 + ks]);
            continue;
        }
        u -= 131072;
        if (u < 262144) {
            int n = u >> 9, ks = kperm_src(u & 511);
            k1wh[u] = __float2half_rn(k1w[ks * 512 + n]);
            continue;
        }
        u -= 262144;
        if (u < 262144) {
            int n = u >> 9, ks = kperm_src(u & 511);
            k2wh[u] = __float2half_rn(k2w[ks * 512 + n]);
            continue;
        }
        u -= 262144;
        if (u < 262144) {
            int n = u >> 9, ks = kperm_src(u & 511);
            l1ph[u] = __float2half_rn(l1w[ks * 512 + n]);
            continue;
        }
        u -= 262144;
        if (u < 262144) {
            int n = u >> 9, ks = kperm_src(u & 511);
            l1eh[u] = __float2half_rn(l1w[(512 + ks) * 512 + n]);
            continue;
        }
        u -= 262144;
        {
            int nt = u >> 15;
            int rem = u & 32767;
            int c = rem >> 11;
            int byte = (rem & 2047) * 2;
            int sub = byte >> 11;
            int tt = (byte >> 9) & 3;
            int gg = (byte >> 6) & 7;
            int y = (byte & 63) ^ (tt * 16);
            int ni = y >> 3;
            int h = (y >> 1) & 3;
            int k = c * 32 + sub * 16 + 2 * tt + ((h >> 1) << 3) + (h & 1);
            int n = nt * 64 + ni * 8 + gg;
            float v = (n < OUT_) ? l2w[k * OUT_ + n] : 0.0f;
            wth[u] = __float2half_rn(v);
        }
    }
}

// ---------------- fp16 MMA GEMM for the small chain (unchanged) ----------------
#define GH_BUF 12288

template <bool OUT16>
__global__ __launch_bounds__(256) void gemm_h(const __half* __restrict__ A0,
                                              const __half* __restrict__ B0,
                                              const float* __restrict__ bias0,
                                              void* __restrict__ out0,
                                              const __half* __restrict__ A1,
                                              const __half* __restrict__ B1,
                                              const float* __restrict__ bias1,
                                              void* __restrict__ out1) {
    __shared__ __align__(16) char sm[3 * GH_BUF];
    const uint32_t sbu = smem_u32(sm);

    const int tid = threadIdx.x;
    const __half* A;
    const __half* B;
    const float* bias;
    void* out;
    int mrow0;
    if (blockIdx.y < 16) {
        A = A0; B = B0; bias = bias0; out = out0; mrow0 = blockIdx.y * 64;
    } else {
        A = A1; B = B1; bias = bias1; out = out1; mrow0 = (blockIdx.y - 16) * 64;
    }
    const int ncol0 = blockIdx.x * 64;

    const int wid = tid >> 5, lane = tid & 31;
    const int g = lane >> 2, t = lane & 3;
    const int mgrp = wid >> 1, nw = (wid & 1) * 32;

    const int srow = tid >> 2, seg = tid & 3;
    const char* a_src = (const char*)(A + (size_t)(mrow0 + srow) * 512);
    const char* b_src = (const char*)(B + (size_t)(ncol0 + srow) * 512);
    const uint32_t a_d = srow * 96u + seg * 16u;
    const uint32_t b_d = 6144u + srow * 96u + seg * 16u;

#define GH_ISSUE(c)                                             \
    do {                                                        \
        uint32_t _b = sbu + ((c) % 3) * GH_BUF;                 \
        cp16(_b + a_d, a_src + (c) * 64 + seg * 16);            \
        cp16(_b + b_d, b_src + (c) * 64 + seg * 16);            \
    } while (0)

    GH_ISSUE(0); CP_COMMIT();
    GH_ISSUE(1); CP_COMMIT();

    float acc[4][4];
#pragma unroll
    for (int ni = 0; ni < 4; ni++)
#pragma unroll
        for (int j = 0; j < 4; j++) acc[ni][j] = 0.0f;

    const int arow = mgrp * 16 + g;

#pragma unroll 1
    for (int c = 0; c < 16; ++c) {
        CP_WAIT1();
        __syncthreads();
        if (c + 2 < 16) { GH_ISSUE(c + 2); CP_COMMIT(); }
        else { CP_COMMIT(); }

        const char* ab = sm + (c % 3) * GH_BUF;
        const char* bb = ab + 6144;
#pragma unroll
        for (int sub = 0; sub < 2; ++sub) {
            const uint32_t ko = sub * 32 + t * 8;
            const uint2 alo = *(const uint2*)(ab + arow * 96 + ko);
            const uint2 ahi = *(const uint2*)(ab + (arow + 8) * 96 + ko);
            uint32_t a[4] = {alo.x, ahi.x, alo.y, ahi.y};
#pragma unroll
            for (int ni = 0; ni < 4; ++ni) {
                const uint2 bv = *(const uint2*)(bb + (nw + ni * 8 + g) * 96 + ko);
                mma16(acc[ni], a, bv.x, bv.y);
            }
        }
    }

    const int m0 = mrow0 + mgrp * 16 + g;
#pragma unroll
    for (int ni = 0; ni < 4; ++ni) {
        const int ncol = ncol0 + nw + ni * 8;
        const int off = (ncol >> 4) * 16 + 4 * t + 2 * (ni & 1);
        const float b0v = bias ? bias[ncol + 2 * t] : 0.0f;
        const float b1v = bias ? bias[ncol + 2 * t + 1] : 0.0f;
        if (OUT16) {
            __half* o = (__half*)out;
            *(uint32_t*)(o + (size_t)m0 * 512 + off) =
                pack_h2(acc[ni][0] + b0v, acc[ni][1] + b1v);
            *(uint32_t*)(o + (size_t)(m0 + 8) * 512 + off) =
                pack_h2(acc[ni][2] + b0v, acc[ni][3] + b1v);
        } else {
            float* o = (float*)out;
            float2 w0 = {acc[ni][0] + b0v, acc[ni][1] + b1v};
            float2 w1 = {acc[ni][2] + b0v, acc[ni][3] + b1v};
            *(float2*)(o + (size_t)m0 * 512 + off) = w0;
            *(float2*)(o + (size_t)(m0 + 8) * 512 + off) = w1;
        }
    }
#undef GH_ISSUE
}

// ---------------- main kernel ----------------
// CTA = (4p, 64e, 64n), 256 thr = 8 warps = 2 p-pairs x 4 e-groups;
// warp = (2p x 16e x 64n): B + ee LDS amortized over 2 p (256B LDS per warp-MMA).
// 4-stage cp.async, 2 CTAs/SM. grid 8192: bid = pg*32 + eq*8 + nt
#define EE_BUF 8192u
#define B_BUF  4096u
#define OFF_B  (4 * EE_BUF)           // 32768
#define OFF_PP (OFF_B + 4 * B_BUF)    // 49152
#define OFF_BI (OFF_PP + 8192u)       // 57344
#define DYN_SMEM (OFF_BI + 256u)      // 57600

__global__ __launch_bounds__(256, 2) void big_kernel(const float* __restrict__ pp,
                                                     const float* __restrict__ ee,
                                                     const __half* __restrict__ wth,
                                                     const float* __restrict__ bias,
                                                     float* __restrict__ out) {
    extern __shared__ char dsm[];
    const uint32_t sbu = smem_u32(dsm);

    const int tid = threadIdx.x;
    const int bid = blockIdx.x;
    const int nt = bid & 7, eq = (bid >> 3) & 3, pg = bid >> 5;
    const int n0 = nt * 64, e0 = eq * 64, p0 = pg * 4;

    const int wid = tid >> 5, lane = tid & 31;
    const int g = lane >> 2, t = lane & 3;
    const int pq = wid >> 2;        // p-pair 0/1
    const int e_g = wid & 3;        // 0..3

    // ---- staging ----
    const int srow = tid >> 2;                   // 0..63
    const int es2 = (tid & 3) * 2;
    const char* ee_src = (const char*)(ee + (size_t)(e0 + srow) * 512);
    const char* wt_src = (const char*)(wth + (size_t)nt * 32768);
    const uint32_t eswz_w = (uint32_t)((srow & 1) * 64);
    const uint32_t ee_d0 = srow * 128u + (((uint32_t)es2 * 16u) ^ eswz_w);
    const uint32_t ee_d1 = srow * 128u + (((uint32_t)(es2 + 1) * 16u) ^ eswz_w);
    const uint32_t b_d = OFF_B + (uint32_t)tid * 16u;

#define ISSUE(c)                                                        \
    do {                                                                \
        uint32_t _st = ((c) & 3);                                       \
        const char* _es = ee_src + (c) * 128;                           \
        cp16(sbu + _st * EE_BUF + ee_d0, _es + es2 * 16);               \
        cp16(sbu + _st * EE_BUF + ee_d1, _es + es2 * 16 + 16);          \
        cp16(sbu + _st * B_BUF + b_d, wt_src + (c) * 4096 + tid * 16);  \
    } while (0)

    ISSUE(0); CP_COMMIT();
    ISSUE(1); CP_COMMIT();
    ISSUE(2); CP_COMMIT();

    float* pp_s = (float*)(dsm + OFF_PP);
    float* bias_s = (float*)(dsm + OFF_BI);
    for (int i = tid; i < 2048; i += 256)
        pp_s[i] = pp[(size_t)(p0 + (i >> 9)) * 512 + (i & 511)];
    if (tid < 64) bias_s[tid] = (n0 + tid < OUT_) ? bias[n0 + tid] : 0.0f;

    float acc[16][4];   // [p(2)][ni(8)][4]
#pragma unroll
    for (int ni = 0; ni < 16; ni++)
#pragma unroll
        for (int j = 0; j < 4; j++) acc[ni][j] = 0.0f;

    // read-side constants
    const int r0 = e_g * 16 + g;
    const uint32_t eswz_r = (uint32_t)((g & 1) * 64);
    const uint32_t aoff[2] = {
        (((uint32_t)(0 * 64 + t * 16)) ^ eswz_r),
        (((uint32_t)(1 * 64 + t * 16)) ^ eswz_r)};
    const uint32_t broff = (uint32_t)(t * 512 + g * 64);
    const uint32_t bxor = (uint32_t)(t * 16);

#pragma unroll 1
    for (int c = 0; c < 16; ++c) {
        CP_WAIT2();
        __syncthreads();
        if (c + 3 < 16) { ISSUE(c + 3); CP_COMMIT(); }
        else { CP_COMMIT(); }

        const char* eb = dsm + (c & 3) * EE_BUF;
        const char* bb = dsm + OFF_B + (c & 3) * B_BUF + broff;
        const float* ppc0 = pp_s + (pq * 2) * 512 + c * 32;
        const float* ppc1 = ppc0 + 512;

#pragma unroll
        for (int sub = 0; sub < 2; ++sub) {
            const float4 pv0 = *(const float4*)(ppc0 + sub * 16 + t * 4);
            const float4 pv1 = *(const float4*)(ppc1 + sub * 16 + t * 4);
            const float4 v0 = *(const float4*)(eb + r0 * 128 + aoff[sub]);
            const float4 v1 = *(const float4*)(eb + (r0 + 8) * 128 + aoff[sub]);
            uint32_t a0[4], a1[4];
            a0[0] = pack_relu_h2(v0.x + pv0.x, v0.y + pv0.y);
            a0[1] = pack_relu_h2(v1.x + pv0.x, v1.y + pv0.y);
            a0[2] = pack_relu_h2(v0.z + pv0.z, v0.w + pv0.w);
            a0[3] = pack_relu_h2(v1.z + pv0.z, v1.w + pv0.w);
            a1[0] = pack_relu_h2(v0.x + pv1.x, v0.y + pv1.y);
            a1[1] = pack_relu_h2(v1.x + pv1.x, v1.y + pv1.y);
            a1[2] = pack_relu_h2(v0.z + pv1.z, v0.w + pv1.w);
            a1[3] = pack_relu_h2(v1.z + pv1.z, v1.w + pv1.w);

            const char* bs = bb + sub * 2048;
            uint4 bq = *(const uint4*)(bs + (0u ^ bxor));
#pragma unroll
            for (int nip = 0; nip < 4; ++nip) {
                uint4 bq_n;
                if (nip < 3)
                    bq_n = *(const uint4*)(bs + (((uint32_t)(nip + 1) * 16u) ^ bxor));
                mma16(acc[2 * nip], a0, bq.x, bq.y);
                mma16(acc[2 * nip + 1], a0, bq.z, bq.w);
                mma16(acc[8 + 2 * nip], a1, bq.x, bq.y);
                mma16(acc[8 + 2 * nip + 1], a1, bq.z, bq.w);
                if (nip < 3) bq = bq_n;
            }
        }
    }

    // ---- epilogue ----
    const int er0 = e0 + e_g * 16 + g;
#pragma unroll
    for (int pq2 = 0; pq2 < 2; ++pq2) {
        const size_t prow = (size_t)(p0 + pq * 2 + pq2) * E_;
        float* o0 = out + (prow + er0) * OUT_;
        float* o1 = out + (prow + er0 + 8) * OUT_;
#pragma unroll
        for (int ni = 0; ni < 8; ++ni) {
            const int ncl = ni * 8 + 2 * t;
            const int n = n0 + ncl;
            if (n < OUT_) {
                const float bz0 = bias_s[ncl], bz1 = bias_s[ncl + 1];
                const float* av = acc[pq2 * 8 + ni];
                float2 w0, w1;
                w0.x = fmaxf(av[0] + bz0, 0.0f);
                w0.y = fmaxf(av[1] + bz1, 0.0f);
                w1.x = fmaxf(av[2] + bz0, 0.0f);
                w1.y = fmaxf(av[3] + bz1, 0.0f);
                *(float2*)(o0 + n) = w0;
                *(float2*)(o1 + n) = w1;
            }
        }
    }
#undef ISSUE
}

// ---------------- launch ----------------
extern "C" void kernel_launch(void* const* d_in, const int* in_sizes, int n_in,
                              void* d_out, int out_size) {
    const float* post  = (const float*)d_in[0];
    const float* emoji = (const float*)d_in[1];
    const float* k1_w  = (const float*)d_in[2];
    const float* k1_b  = (const float*)d_in[3];
    const float* k2_w  = (const float*)d_in[4];
    const float* k2_b  = (const float*)d_in[5];
    const float* l1_w  = (const float*)d_in[6];
    const float* l1_b  = (const float*)d_in[7];
    const float* l2_w  = (const float*)d_in[8];
    const float* l2_b  = (const float*)d_in[9];
    float* out = (float*)d_out;

    __half *pPH, *pEH, *pK1, *pK2, *pL1P, *pL1E, *pPh, *pEh, *pWT;
    float *pPP, *pEE;
    cudaGetSymbolAddress((void**)&pPH, g_posth);
    cudaGetSymbolAddress((void**)&pEH, g_emojih);
    cudaGetSymbolAddress((void**)&pK1, g_k1wh);
    cudaGetSymbolAddress((void**)&pK2, g_k2wh);
    cudaGetSymbolAddress((void**)&pL1P, g_l1ph);
    cudaGetSymbolAddress((void**)&pL1E, g_l1eh);
    cudaGetSymbolAddress((void**)&pPh, g_ph);
    cudaGetSymbolAddress((void**)&pEh, g_eh);
    cudaGetSymbolAddress((void**)&pPP, g_pp);
    cudaGetSymbolAddress((void**)&pEE, g_ee);
    cudaGetSymbolAddress((void**)&pWT, g_wth);

    cudaFuncSetAttribute(big_kernel, cudaFuncAttributeMaxDynamicSharedMemorySize,
                         DYN_SMEM);

    prep<<<960, 256>>>(post, emoji, k1_w, k2_w, l1_w, l2_w,
                       pPH, pEH, pK1, pK2, pL1P, pL1E, pWT);
    gemm_h<true><<<dim3(8, 20), 256>>>(pPH, pK1, k1_b, pPh,
                                       pEH, pK2, k2_b, pEh);
    gemm_h<false><<<dim3(8, 20), 256>>>(pPh, pL1P, nullptr, pPP,
                                        pEh, pL1E, l1_b, pEE);
    big_kernel<<<8192, 256, DYN_SMEM>>>(pPP, pEE, pWT, l2_b, out);
}